// round 1
// baseline (speedup 1.0000x reference)
#include <cuda_runtime.h>

// Problem constants (fixed by setup_inputs)
#define BATCH   2
#define SEQ     2048
#define DMODEL  2048
#define NHEADS  16
#define DH      128
#define NROWS   (BATCH*SEQ)          // 4096
#define CHUNK   ((size_t)NROWS*DMODEL) // 8388608 elements per output tensor

// Scratch (allocation-free rule: __device__ globals)
__device__ float g_q[(size_t)BATCH*NHEADS*SEQ*DH];   // Q in [B,H,S,Dh], pre-scaled
__device__ float g_ctx[(size_t)NROWS*DMODEL];        // attention context [B,S,D]

// ---------------------------------------------------------------------------
// SGEMM: C = scale * (A[4096,2048] @ W[2048,2048] + bias)
// qkv_mode==0: C row-major [4096,2048]
// qkv_mode==1: C in [B,H,S,Dh] layout (row=(b,s), col=(h,dh))
// BM=BN=128, BK=16, 256 threads, 8x8 microtile
// ---------------------------------------------------------------------------
__global__ __launch_bounds__(256) void sgemm_bias_kernel(
    const float* __restrict__ A, const float* __restrict__ W,
    const float* __restrict__ bias, float* __restrict__ C,
    float scale, int qkv_mode)
{
    const int K = DMODEL, N = DMODEL;
    __shared__ float As[16][128];   // transposed: As[k][m]
    __shared__ float Bs[16][128];   // Bs[k][n]

    const int tid = threadIdx.x;
    const int tn = tid & 15;        // 0..15
    const int tm = tid >> 4;        // 0..15
    const int bx = blockIdx.x;      // N tile (16)
    const int by = blockIdx.y;      // M tile (32)

    const float* Ab = A + (size_t)(by * 128) * K;
    const float* Wb = W + bx * 128;

    const int a_row = tid >> 1;          // 0..127
    const int a_col = (tid & 1) * 8;     // 0 or 8
    const int b_row = tid >> 5;          // 0..7
    const int b_c4  = tid & 31;          // 0..31

    float acc[8][8];
    #pragma unroll
    for (int i = 0; i < 8; i++)
        #pragma unroll
        for (int j = 0; j < 8; j++) acc[i][j] = 0.f;

    for (int k0 = 0; k0 < K; k0 += 16) {
        float4 a0 = *(const float4*)(Ab + (size_t)a_row * K + k0 + a_col);
        float4 a1 = *(const float4*)(Ab + (size_t)a_row * K + k0 + a_col + 4);
        float4 w0 = *(const float4*)(Wb + (size_t)(k0 + b_row) * N + b_c4 * 4);
        float4 w1 = *(const float4*)(Wb + (size_t)(k0 + b_row + 8) * N + b_c4 * 4);

        __syncthreads();   // previous compute done before overwriting tiles
        As[a_col + 0][a_row] = a0.x;
        As[a_col + 1][a_row] = a0.y;
        As[a_col + 2][a_row] = a0.z;
        As[a_col + 3][a_row] = a0.w;
        As[a_col + 4][a_row] = a1.x;
        As[a_col + 5][a_row] = a1.y;
        As[a_col + 6][a_row] = a1.z;
        As[a_col + 7][a_row] = a1.w;
        *(float4*)&Bs[b_row][b_c4 * 4]     = w0;
        *(float4*)&Bs[b_row + 8][b_c4 * 4] = w1;
        __syncthreads();

        #pragma unroll
        for (int kk = 0; kk < 16; kk++) {
            float4 ar0 = *(const float4*)&As[kk][tm * 8];
            float4 ar1 = *(const float4*)&As[kk][tm * 8 + 4];
            float4 br0 = *(const float4*)&Bs[kk][tn * 8];
            float4 br1 = *(const float4*)&Bs[kk][tn * 8 + 4];
            float ar[8] = {ar0.x, ar0.y, ar0.z, ar0.w, ar1.x, ar1.y, ar1.z, ar1.w};
            float br[8] = {br0.x, br0.y, br0.z, br0.w, br1.x, br1.y, br1.z, br1.w};
            #pragma unroll
            for (int i = 0; i < 8; i++)
                #pragma unroll
                for (int j = 0; j < 8; j++)
                    acc[i][j] += ar[i] * br[j];
        }
    }

    // Epilogue
    float bv[8];
    #pragma unroll
    for (int j = 0; j < 8; j++) bv[j] = bias[bx * 128 + tn * 8 + j];

    #pragma unroll
    for (int i = 0; i < 8; i++) {
        const int row = by * 128 + tm * 8 + i;
        float4 r0, r1;
        r0.x = (acc[i][0] + bv[0]) * scale;
        r0.y = (acc[i][1] + bv[1]) * scale;
        r0.z = (acc[i][2] + bv[2]) * scale;
        r0.w = (acc[i][3] + bv[3]) * scale;
        r1.x = (acc[i][4] + bv[4]) * scale;
        r1.y = (acc[i][5] + bv[5]) * scale;
        r1.z = (acc[i][6] + bv[6]) * scale;
        r1.w = (acc[i][7] + bv[7]) * scale;
        if (qkv_mode == 0) {
            float* dst = C + (size_t)row * N + bx * 128 + tn * 8;
            *(float4*)(dst)     = r0;
            *(float4*)(dst + 4) = r1;
        } else {
            // col block bx covers exactly head h = bx (128 cols == Dh)
            const int bb = row >> 11;        // / SEQ
            const int ss = row & 2047;       // % SEQ
            float* dst = C + (((size_t)(bb * NHEADS + bx) * SEQ + ss) * DH) + tn * 8;
            *(float4*)(dst)     = r0;
            *(float4*)(dst + 4) = r1;
        }
    }
}

// ---------------------------------------------------------------------------
// Flash attention (causal, fp32). One block = 128 query rows of one (b,h).
// One thread = one query row; O[128] in registers; K/V tiles (32x128) in smem.
// Q is pre-scaled by 1/sqrt(Dh).
// ---------------------------------------------------------------------------
#define QS_STRIDE 132
#define BN_ATT 32
#define ATTN_SMEM ((128*QS_STRIDE + 2*BN_ATT*DH) * 4)

__global__ __launch_bounds__(128) void attn_kernel(
    const float* __restrict__ Kg, const float* __restrict__ Vg)
{
    extern __shared__ float sm[];
    float* Qs = sm;                          // 128 x 132 (padded)
    float* Ks = sm + 128 * QS_STRIDE;        // 32 x 128
    float* Vs = Ks + BN_ATT * DH;            // 32 x 128

    const int t  = threadIdx.x;
    const int q0 = blockIdx.x * 128;
    const int h  = blockIdx.y;
    const int b  = blockIdx.z;

    const size_t headoff = (size_t)(b * NHEADS + h) * SEQ * DH;
    const float* qbase = g_q + headoff;
    const float* kbase = Kg + headoff;
    const float* vbase = Vg + headoff;

    // Load Q tile (coalesced)
    for (int idx = t; idx < 128 * 32; idx += 128) {
        int row = idx >> 5, c = (idx & 31) * 4;
        *(float4*)&Qs[row * QS_STRIDE + c] =
            *(const float4*)&qbase[(size_t)(q0 + row) * DH + c];
    }

    float o[DH];
    #pragma unroll
    for (int d = 0; d < DH; d++) o[d] = 0.f;
    float m = -1e30f, l = 0.f;
    const int qi = q0 + t;

    const int nkt = (q0 >> 5) + 4;  // tiles covering keys 0 .. q0+127
    for (int kt = 0; kt < nkt; kt++) {
        const int k0 = kt * BN_ATT;
        __syncthreads();
        for (int idx = t; idx < BN_ATT * 32; idx += 128) {
            int row = idx >> 5, c = (idx & 31) * 4;
            *(float4*)&Ks[row * DH + c] =
                *(const float4*)&kbase[(size_t)(k0 + row) * DH + c];
            *(float4*)&Vs[row * DH + c] =
                *(const float4*)&vbase[(size_t)(k0 + row) * DH + c];
        }
        __syncthreads();

        // Scores s[j] = Qrow . K_j (scale folded into Q)
        float s[BN_ATT];
        #pragma unroll
        for (int j = 0; j < BN_ATT; j++) s[j] = 0.f;
        for (int d0 = 0; d0 < DH; d0 += 4) {
            float4 q4 = *(const float4*)&Qs[t * QS_STRIDE + d0];
            #pragma unroll
            for (int j = 0; j < BN_ATT; j++) {
                float4 k4 = *(const float4*)&Ks[j * DH + d0];   // broadcast
                s[j] += q4.x * k4.x + q4.y * k4.y + q4.z * k4.z + q4.w * k4.w;
            }
        }
        if (k0 + BN_ATT - 1 > q0) {     // tile may cross causal boundary
            #pragma unroll
            for (int j = 0; j < BN_ATT; j++)
                if (k0 + j > qi) s[j] = -1e30f;
        }

        float mnew = m;
        #pragma unroll
        for (int j = 0; j < BN_ATT; j++) mnew = fmaxf(mnew, s[j]);
        float alpha = __expf(m - mnew);
        l *= alpha;
        #pragma unroll
        for (int d = 0; d < DH; d++) o[d] *= alpha;

        #pragma unroll
        for (int j = 0; j < BN_ATT; j++) {
            float p = __expf(s[j] - mnew);
            l += p;
            #pragma unroll
            for (int d0 = 0; d0 < DH; d0 += 4) {
                float4 v4 = *(const float4*)&Vs[j * DH + d0];   // broadcast
                o[d0]     += p * v4.x;
                o[d0 + 1] += p * v4.y;
                o[d0 + 2] += p * v4.z;
                o[d0 + 3] += p * v4.w;
            }
        }
        m = mnew;
    }

    const float inv = 1.f / l;
    float* crow = g_ctx + ((size_t)(b * SEQ + qi)) * DMODEL + h * DH;
    #pragma unroll
    for (int d0 = 0; d0 < DH; d0 += 4) {
        float4 r;
        r.x = o[d0] * inv; r.y = o[d0 + 1] * inv;
        r.z = o[d0 + 2] * inv; r.w = o[d0 + 3] * inv;
        *(float4*)&crow[d0] = r;
    }
}

// ---------------------------------------------------------------------------
// Residual + LayerNorm: ln = gamma*(y-mu)*rsqrt(var+eps)+beta, y = attn_out + x
// One block per row (4096 blocks, 256 threads)
// ---------------------------------------------------------------------------
__global__ __launch_bounds__(256) void ln_kernel(
    const float* __restrict__ x, const float* __restrict__ ao,
    const float* __restrict__ gamma, const float* __restrict__ beta,
    float* __restrict__ out)
{
    __shared__ float ys[DMODEL];
    __shared__ float s_part[16];
    __shared__ float s_mu, s_rstd;

    const int r = blockIdx.x;
    const int t = threadIdx.x;
    const float* xr = x + (size_t)r * DMODEL;
    const float* ar = ao + (size_t)r * DMODEL;

    float sum = 0.f, sq = 0.f;
    for (int d = t; d < DMODEL; d += 256) {
        float y = xr[d] + ar[d];
        ys[d] = y;
        sum += y;
        sq  += y * y;
    }
    #pragma unroll
    for (int off = 16; off > 0; off >>= 1) {
        sum += __shfl_xor_sync(0xffffffffu, sum, off);
        sq  += __shfl_xor_sync(0xffffffffu, sq, off);
    }
    const int wid = t >> 5, lane = t & 31;
    if (lane == 0) { s_part[wid] = sum; s_part[8 + wid] = sq; }
    __syncthreads();
    if (t == 0) {
        float S = 0.f, Q = 0.f;
        #pragma unroll
        for (int w = 0; w < 8; w++) { S += s_part[w]; Q += s_part[8 + w]; }
        float mu  = S * (1.f / DMODEL);
        float var = Q * (1.f / DMODEL) - mu * mu;
        s_mu = mu;
        s_rstd = rsqrtf(var + 1e-5f);
    }
    __syncthreads();
    const float mu = s_mu, rstd = s_rstd;
    float* outr = out + (size_t)r * DMODEL;
    for (int d = t; d < DMODEL; d += 256)
        outr[d] = gamma[d] * (ys[d] - mu) * rstd + beta[d];
}

// ---------------------------------------------------------------------------
extern "C" void kernel_launch(void* const* d_in, const int* in_sizes, int n_in,
                              void* d_out, int out_size)
{
    const float* x     = (const float*)d_in[0];
    const float* Wq    = (const float*)d_in[1];
    const float* bq    = (const float*)d_in[2];
    const float* Wk    = (const float*)d_in[3];
    const float* bk    = (const float*)d_in[4];
    const float* Wv    = (const float*)d_in[5];
    const float* bv    = (const float*)d_in[6];
    const float* Wo    = (const float*)d_in[7];
    const float* bo    = (const float*)d_in[8];
    const float* gamma = (const float*)d_in[9];
    const float* beta  = (const float*)d_in[10];

    float* out    = (float*)d_out;
    float* ln_out = out;             // section 0: ln
    float* ao_out = out + CHUNK;     // section 1: attn_out
    float* k_out  = out + 2 * CHUNK; // section 2: k [B,H,S,Dh]
    float* v_out  = out + 3 * CHUNK; // section 3: v [B,H,S,Dh]

    float* qptr   = nullptr;
    float* ctxptr = nullptr;
    cudaGetSymbolAddress((void**)&qptr, g_q);
    cudaGetSymbolAddress((void**)&ctxptr, g_ctx);

    cudaFuncSetAttribute(attn_kernel,
                         cudaFuncAttributeMaxDynamicSharedMemorySize, ATTN_SMEM);

    const float qscale = 0.08838834764831845f;  // 1/sqrt(128)
    dim3 gemm_grid(DMODEL / 128, NROWS / 128);  // (16, 32)

    // Q/K/V projections ([B,H,S,Dh] layout; Q pre-scaled)
    sgemm_bias_kernel<<<gemm_grid, 256>>>(x, Wq, bq, qptr,  qscale, 1);
    sgemm_bias_kernel<<<gemm_grid, 256>>>(x, Wk, bk, k_out, 1.0f,   1);
    sgemm_bias_kernel<<<gemm_grid, 256>>>(x, Wv, bv, v_out, 1.0f,   1);

    // Causal flash attention -> g_ctx [B,S,D]
    dim3 attn_grid(SEQ / 128, NHEADS, BATCH);   // (16,16,2)
    attn_kernel<<<attn_grid, 128, ATTN_SMEM>>>(k_out, v_out);

    // Output projection: attn_out = ctx @ Wo + bo
    sgemm_bias_kernel<<<gemm_grid, 256>>>(ctxptr, Wo, bo, ao_out, 1.0f, 0);

    // Residual + LayerNorm
    ln_kernel<<<NROWS, 256>>>(x, ao_out, gamma, beta, ln_out);
}

// round 3
// speedup vs baseline: 1.8272x; 1.8272x over previous
#include <cuda_runtime.h>
#include <cstdint>

// ---------------------------------------------------------------------------
// Problem constants
// ---------------------------------------------------------------------------
#define BATCH   2
#define SEQ     2048
#define DMODEL  2048
#define NHEADS  16
#define DH      128
#define NROWS   (BATCH*SEQ)              // 4096
#define CHUNK_E ((size_t)NROWS*DMODEL)

// Scratch (__device__ globals: allocation-free rule)
__device__ float g_q  [(size_t)BATCH*NHEADS*SEQ*DH];   // Q [B,H,S,Dh], pre-scaled
__device__ float g_ctx[(size_t)NROWS*DMODEL];          // attention ctx (tf32-rounded)
__device__ float g_wt [4ULL*DMODEL*DMODEL];            // W^T (tf32-rounded)
__device__ float g_x  [(size_t)NROWS*DMODEL];          // x (tf32-rounded)

// ---------------------------------------------------------------------------
// PTX helpers (baseline features only: work under compute_103)
// ---------------------------------------------------------------------------
__device__ __forceinline__ uint32_t smem_u32(const void* p) {
    uint32_t a;
    asm("{ .reg .u64 t; cvta.to.shared.u64 t, %1; cvt.u32.u64 %0, t; }"
        : "=r"(a) : "l"(p));
    return a;
}
__device__ __forceinline__ float tf32r(float x) {
    float r;
    asm("cvt.rna.tf32.f32 %0, %1;" : "=f"(r) : "f"(x));
    return r;
}
#define CP_ASYNC16(dst, src) \
    asm volatile("cp.async.cg.shared.global [%0], [%1], 16;" :: "r"(dst), "l"(src))
#define CP_COMMIT()  asm volatile("cp.async.commit_group;" ::: "memory")
#define CP_WAIT1()   asm volatile("cp.async.wait_group 1;" ::: "memory")
#define CP_WAIT0()   asm volatile("cp.async.wait_group 0;" ::: "memory")

__device__ __forceinline__ void ldsm_x4(uint32_t& r0, uint32_t& r1,
                                        uint32_t& r2, uint32_t& r3, uint32_t a) {
    asm volatile("ldmatrix.sync.aligned.m8n8.x4.shared.b16 {%0,%1,%2,%3}, [%4];"
                 : "=r"(r0), "=r"(r1), "=r"(r2), "=r"(r3) : "r"(a));
}
__device__ __forceinline__ void mma_tf32(float* c, const uint32_t* a,
                                         uint32_t b0, uint32_t b1) {
    asm volatile(
        "mma.sync.aligned.m16n8k8.row.col.f32.tf32.tf32.f32 "
        "{%0,%1,%2,%3},{%4,%5,%6,%7},{%8,%9},{%0,%1,%2,%3};"
        : "+f"(c[0]), "+f"(c[1]), "+f"(c[2]), "+f"(c[3])
        : "r"(a[0]), "r"(a[1]), "r"(a[2]), "r"(a[3]), "r"(b0), "r"(b1));
}

// ---------------------------------------------------------------------------
// x -> tf32-rounded copy
// ---------------------------------------------------------------------------
__global__ __launch_bounds__(256) void round_tf32_kernel(
    const float* __restrict__ in, float* __restrict__ out)
{
    const int i = blockIdx.x * 256 + threadIdx.x;
    float4 v = ((const float4*)in)[i];
    v.x = tf32r(v.x); v.y = tf32r(v.y); v.z = tf32r(v.z); v.w = tf32r(v.w);
    ((float4*)out)[i] = v;
}

// ---------------------------------------------------------------------------
// Weight transpose (+ tf32 rounding): out[n][k] = round(in[k][n])
// ---------------------------------------------------------------------------
__global__ __launch_bounds__(256) void transpose_kernel(
    const float* __restrict__ in, float* __restrict__ out)
{
    __shared__ float t[32][33];
    const int x  = blockIdx.x * 32 + threadIdx.x;
    const int y0 = blockIdx.y * 32 + threadIdx.y;
    #pragma unroll
    for (int j = 0; j < 4; j++)
        t[threadIdx.y + j * 8][threadIdx.x] = in[(size_t)(y0 + j * 8) * DMODEL + x];
    __syncthreads();
    const int x2  = blockIdx.y * 32 + threadIdx.x;
    const int y20 = blockIdx.x * 32 + threadIdx.y;
    #pragma unroll
    for (int j = 0; j < 4; j++)
        out[(size_t)(y20 + j * 8) * DMODEL + x2] =
            tf32r(t[threadIdx.x][threadIdx.y + j * 8]);
}

// ---------------------------------------------------------------------------
// TF32 mma.sync GEMM: C = scale * (A[4096,2048] @ Bt^T + bias)
//   A [M,K] row-major (tf32-rounded), Bt [N,K] row-major (tf32-rounded).
//   128x128 CTA tile, BK=32, cp.async double buffer, 8 warps of 64x32.
//   qkv_mode 0: row-major out; 1: [B,H,S,Dh] out (BN==Dh==128, head==bx).
// ---------------------------------------------------------------------------
#define BK 32
#define NCHUNK (DMODEL / BK)          // 64
#define LDS_STRIDE 36                 // floats, pad 4
#define TILE_B (128 * LDS_STRIDE * 4) // 18432 bytes per tile buffer
#define SA0 0
#define SA1 TILE_B
#define SB0 (2 * TILE_B)
#define SB1 (3 * TILE_B)
#define GEMM_SMEM (4 * TILE_B)        // 73728

__global__ __launch_bounds__(256, 2) void gemm_tf32_kernel(
    const float* __restrict__ A, const float* __restrict__ Bt,
    const float* __restrict__ bias, float* __restrict__ C,
    float scale, int qkv_mode)
{
    extern __shared__ char smc[];
    const uint32_t sb = smem_u32(smc);
    const int tid = threadIdx.x;
    const int wid = tid >> 5, lane = tid & 31;
    const int bx = blockIdx.x, by = blockIdx.y;

    const float* Ab = A  + (size_t)(by * 128) * DMODEL;
    const float* Bb = Bt + (size_t)(bx * 128) * DMODEL;

    // ---- global -> smem (cp.async), [row][k] with stride 36 floats ----
    const int grow = tid >> 3;            // 0..31
    const int gcol = (tid & 7) * 4;       // 0,4,..,28
    auto load_chunk = [&](int chunk, int p) {
        const float* as = Ab + (size_t)grow * DMODEL + chunk * BK + gcol;
        const float* bs = Bb + (size_t)grow * DMODEL + chunk * BK + gcol;
        const uint32_t ad = sb + (p ? SA1 : SA0) + grow * (LDS_STRIDE * 4) + gcol * 4;
        const uint32_t bd = sb + (p ? SB1 : SB0) + grow * (LDS_STRIDE * 4) + gcol * 4;
        #pragma unroll
        for (int r = 0; r < 4; r++) {
            CP_ASYNC16(ad + r * 32 * (LDS_STRIDE * 4), as + (size_t)r * 32 * DMODEL);
            CP_ASYNC16(bd + r * 32 * (LDS_STRIDE * 4), bs + (size_t)r * 32 * DMODEL);
        }
    };

    // ---- ldmatrix source addresses ----
    const int wm = wid & 1;               // 0..1  -> M offset 64*wm
    const int wn = wid >> 1;              // 0..3  -> N offset 32*wn
    const int r7  = lane & 7;
    const int sel = lane >> 3;            // 0..3

    uint32_t aAddr[2][4], bAddr[2][2];
    {
        // A matrices per mtile: sel0:{m+r7,k0} sel1:{m+8+r7,k0} sel2:{m+r7,k4} sel3:{m+8+r7,k4}
        const int arow = wm * 64 + (sel & 1) * 8 + r7;
        const int acol = (sel >> 1) * 4;
        // B matrices per ntile-pair: sel0:{n+r7,k0} sel1:{n+r7,k4} sel2:{n+8+r7,k0} sel3:{n+8+r7,k4}
        const int brow = wn * 32 + (sel >> 1) * 8 + r7;
        const int bcol = (sel & 1) * 4;
        #pragma unroll
        for (int p = 0; p < 2; p++) {
            #pragma unroll
            for (int mt = 0; mt < 4; mt++)
                aAddr[p][mt] = sb + (p ? SA1 : SA0)
                             + (arow + mt * 16) * (LDS_STRIDE * 4) + acol * 4;
            #pragma unroll
            for (int np = 0; np < 2; np++)
                bAddr[p][np] = sb + (p ? SB1 : SB0)
                             + (brow + np * 16) * (LDS_STRIDE * 4) + bcol * 4;
        }
    }

    float acc[4][4][4];
    #pragma unroll
    for (int mt = 0; mt < 4; mt++)
        #pragma unroll
        for (int nt = 0; nt < 4; nt++)
            #pragma unroll
            for (int q = 0; q < 4; q++) acc[mt][nt][q] = 0.f;

    // ---- pipeline ----
    load_chunk(0, 0); CP_COMMIT();
    load_chunk(1, 1); CP_COMMIT();

    for (int i = 0; i < NCHUNK; i++) {
        const int p = i & 1;
        if (i + 2 < NCHUNK) { CP_WAIT1(); } else { CP_WAIT0(); }
        __syncthreads();

        #pragma unroll
        for (int ks = 0; ks < 4; ks++) {
            uint32_t a[4][4], b[2][4];
            #pragma unroll
            for (int mt = 0; mt < 4; mt++)
                ldsm_x4(a[mt][0], a[mt][1], a[mt][2], a[mt][3],
                        aAddr[p][mt] + ks * 32);
            #pragma unroll
            for (int np = 0; np < 2; np++)
                ldsm_x4(b[np][0], b[np][1], b[np][2], b[np][3],
                        bAddr[p][np] + ks * 32);
            #pragma unroll
            for (int mt = 0; mt < 4; mt++)
                #pragma unroll
                for (int nt = 0; nt < 4; nt++)
                    mma_tf32(acc[mt][nt], a[mt],
                             b[nt >> 1][(nt & 1) * 2], b[nt >> 1][(nt & 1) * 2 + 1]);
        }

        __syncthreads();
        if (i + 2 < NCHUNK) { load_chunk(i + 2, p); CP_COMMIT(); }
    }

    // ---- epilogue ----
    const int qr = lane >> 2;          // 0..7
    const int qc = (lane & 3) * 2;     // 0,2,4,6
    #pragma unroll
    for (int nt = 0; nt < 4; nt++) {
        const int dh = wn * 32 + nt * 8 + qc;            // col within 128-tile
        const float bv0 = bias[bx * 128 + dh];
        const float bv1 = bias[bx * 128 + dh + 1];
        #pragma unroll
        for (int mt = 0; mt < 4; mt++) {
            #pragma unroll
            for (int half = 0; half < 2; half++) {
                const int mrow = by * 128 + wm * 64 + mt * 16 + half * 8 + qr;
                float2 r;
                r.x = (acc[mt][nt][half * 2 + 0] + bv0) * scale;
                r.y = (acc[mt][nt][half * 2 + 1] + bv1) * scale;
                float* dst;
                if (qkv_mode == 0) {
                    dst = C + (size_t)mrow * DMODEL + bx * 128 + dh;
                } else {
                    const int b = mrow >> 11, s = mrow & 2047;
                    dst = C + (((size_t)(b * NHEADS + bx) * SEQ + s) * DH) + dh;
                }
                *(float2*)dst = r;
            }
        }
    }
}

// ---------------------------------------------------------------------------
// Flash attention (causal, fp32 SIMT). ctx written tf32-rounded (feeds o-GEMM).
// ---------------------------------------------------------------------------
#define QS_STRIDE 132
#define BN_ATT 32
#define ATTN_SMEM ((128*QS_STRIDE + 2*BN_ATT*DH) * 4)

__global__ __launch_bounds__(128) void attn_kernel(
    const float* __restrict__ Kg, const float* __restrict__ Vg)
{
    extern __shared__ float smf[];
    float* Qs = smf;
    float* Ks = smf + 128 * QS_STRIDE;
    float* Vs = Ks + BN_ATT * DH;

    const int t  = threadIdx.x;
    const int q0 = blockIdx.x * 128;
    const int h  = blockIdx.y;
    const int b  = blockIdx.z;

    const size_t headoff = (size_t)(b * NHEADS + h) * SEQ * DH;
    const float* qbase = g_q + headoff;
    const float* kbase = Kg + headoff;
    const float* vbase = Vg + headoff;

    for (int idx = t; idx < 128 * 32; idx += 128) {
        int row = idx >> 5, c = (idx & 31) * 4;
        *(float4*)&Qs[row * QS_STRIDE + c] =
            *(const float4*)&qbase[(size_t)(q0 + row) * DH + c];
    }

    float o[DH];
    #pragma unroll
    for (int d = 0; d < DH; d++) o[d] = 0.f;
    float m = -1e30f, l = 0.f;
    const int qi = q0 + t;

    const int nkt = (q0 >> 5) + 4;
    for (int kt = 0; kt < nkt; kt++) {
        const int k0 = kt * BN_ATT;
        __syncthreads();
        for (int idx = t; idx < BN_ATT * 32; idx += 128) {
            int row = idx >> 5, c = (idx & 31) * 4;
            *(float4*)&Ks[row * DH + c] =
                *(const float4*)&kbase[(size_t)(k0 + row) * DH + c];
            *(float4*)&Vs[row * DH + c] =
                *(const float4*)&vbase[(size_t)(k0 + row) * DH + c];
        }
        __syncthreads();

        float s[BN_ATT];
        #pragma unroll
        for (int j = 0; j < BN_ATT; j++) s[j] = 0.f;
        for (int d0 = 0; d0 < DH; d0 += 4) {
            float4 q4 = *(const float4*)&Qs[t * QS_STRIDE + d0];
            #pragma unroll
            for (int j = 0; j < BN_ATT; j++) {
                float4 k4 = *(const float4*)&Ks[j * DH + d0];
                s[j] += q4.x * k4.x + q4.y * k4.y + q4.z * k4.z + q4.w * k4.w;
            }
        }
        if (k0 + BN_ATT - 1 > q0) {
            #pragma unroll
            for (int j = 0; j < BN_ATT; j++)
                if (k0 + j > qi) s[j] = -1e30f;
        }

        float mnew = m;
        #pragma unroll
        for (int j = 0; j < BN_ATT; j++) mnew = fmaxf(mnew, s[j]);
        float alpha = __expf(m - mnew);
        l *= alpha;
        #pragma unroll
        for (int d = 0; d < DH; d++) o[d] *= alpha;

        #pragma unroll
        for (int j = 0; j < BN_ATT; j++) {
            float p = __expf(s[j] - mnew);
            l += p;
            #pragma unroll
            for (int d0 = 0; d0 < DH; d0 += 4) {
                float4 v4 = *(const float4*)&Vs[j * DH + d0];
                o[d0]     += p * v4.x;
                o[d0 + 1] += p * v4.y;
                o[d0 + 2] += p * v4.z;
                o[d0 + 3] += p * v4.w;
            }
        }
        m = mnew;
    }

    const float inv = 1.f / l;
    float* crow = g_ctx + ((size_t)(b * SEQ + qi)) * DMODEL + h * DH;
    #pragma unroll
    for (int d0 = 0; d0 < DH; d0 += 4) {
        float4 r;
        r.x = tf32r(o[d0] * inv);     r.y = tf32r(o[d0 + 1] * inv);
        r.z = tf32r(o[d0 + 2] * inv); r.w = tf32r(o[d0 + 3] * inv);
        *(float4*)&crow[d0] = r;
    }
}

// ---------------------------------------------------------------------------
// Residual + LayerNorm
// ---------------------------------------------------------------------------
__global__ __launch_bounds__(256) void ln_kernel(
    const float* __restrict__ x, const float* __restrict__ ao,
    const float* __restrict__ gamma, const float* __restrict__ beta,
    float* __restrict__ out)
{
    __shared__ float ys[DMODEL];
    __shared__ float s_part[16];
    __shared__ float s_mu, s_rstd;

    const int r = blockIdx.x;
    const int t = threadIdx.x;
    const float* xr = x + (size_t)r * DMODEL;
    const float* ar = ao + (size_t)r * DMODEL;

    float sum = 0.f, sq = 0.f;
    for (int d = t; d < DMODEL; d += 256) {
        float y = xr[d] + ar[d];
        ys[d] = y;
        sum += y;
        sq  += y * y;
    }
    #pragma unroll
    for (int off = 16; off > 0; off >>= 1) {
        sum += __shfl_xor_sync(0xffffffffu, sum, off);
        sq  += __shfl_xor_sync(0xffffffffu, sq, off);
    }
    const int wid = t >> 5, lane = t & 31;
    if (lane == 0) { s_part[wid] = sum; s_part[8 + wid] = sq; }
    __syncthreads();
    if (t == 0) {
        float S = 0.f, Q = 0.f;
        #pragma unroll
        for (int w = 0; w < 8; w++) { S += s_part[w]; Q += s_part[8 + w]; }
        float mu  = S * (1.f / DMODEL);
        float var = Q * (1.f / DMODEL) - mu * mu;
        s_mu = mu;
        s_rstd = rsqrtf(var + 1e-5f);
    }
    __syncthreads();
    const float mu = s_mu, rstd = s_rstd;
    float* outr = out + (size_t)r * DMODEL;
    for (int d = t; d < DMODEL; d += 256)
        outr[d] = gamma[d] * (ys[d] - mu) * rstd + beta[d];
}

// ---------------------------------------------------------------------------
extern "C" void kernel_launch(void* const* d_in, const int* in_sizes, int n_in,
                              void* d_out, int out_size)
{
    const float* x     = (const float*)d_in[0];
    const float* Wq    = (const float*)d_in[1];
    const float* bq    = (const float*)d_in[2];
    const float* Wk    = (const float*)d_in[3];
    const float* bk    = (const float*)d_in[4];
    const float* Wv    = (const float*)d_in[5];
    const float* bv    = (const float*)d_in[6];
    const float* Wo    = (const float*)d_in[7];
    const float* bo    = (const float*)d_in[8];
    const float* gamma = (const float*)d_in[9];
    const float* beta  = (const float*)d_in[10];

    float* out    = (float*)d_out;
    float* ln_out = out;
    float* ao_out = out + CHUNK_E;
    float* k_out  = out + 2 * CHUNK_E;   // [B,H,S,Dh]
    float* v_out  = out + 3 * CHUNK_E;   // [B,H,S,Dh]

    float *qptr = nullptr, *ctxptr = nullptr, *wtptr = nullptr, *xptr = nullptr;
    cudaGetSymbolAddress((void**)&qptr,   g_q);
    cudaGetSymbolAddress((void**)&ctxptr, g_ctx);
    cudaGetSymbolAddress((void**)&wtptr,  g_wt);
    cudaGetSymbolAddress((void**)&xptr,   g_x);
    float* wt_q = wtptr;
    float* wt_k = wtptr + 1ULL * DMODEL * DMODEL;
    float* wt_v = wtptr + 2ULL * DMODEL * DMODEL;
    float* wt_o = wtptr + 3ULL * DMODEL * DMODEL;

    cudaFuncSetAttribute(gemm_tf32_kernel,
                         cudaFuncAttributeMaxDynamicSharedMemorySize, GEMM_SMEM);
    cudaFuncSetAttribute(attn_kernel,
                         cudaFuncAttributeMaxDynamicSharedMemorySize, ATTN_SMEM);

    // Pre-round x and W^T to tf32 (keeps mma inputs unbiased-rounded)
    round_tf32_kernel<<<(int)(CHUNK_E / 4 / 256), 256>>>(x, xptr);
    dim3 tg(DMODEL / 32, DMODEL / 32), tb(32, 8);
    transpose_kernel<<<tg, tb>>>(Wq, wt_q);
    transpose_kernel<<<tg, tb>>>(Wk, wt_k);
    transpose_kernel<<<tg, tb>>>(Wv, wt_v);
    transpose_kernel<<<tg, tb>>>(Wo, wt_o);

    const float qscale = 0.08838834764831845f;  // 1/sqrt(128)
    dim3 gemm_grid(DMODEL / 128, NROWS / 128);  // (16, 32)

    gemm_tf32_kernel<<<gemm_grid, 256, GEMM_SMEM>>>(xptr, wt_q, bq, qptr,  qscale, 1);
    gemm_tf32_kernel<<<gemm_grid, 256, GEMM_SMEM>>>(xptr, wt_k, bk, k_out, 1.0f,   1);
    gemm_tf32_kernel<<<gemm_grid, 256, GEMM_SMEM>>>(xptr, wt_v, bv, v_out, 1.0f,   1);

    dim3 attn_grid(SEQ / 128, NHEADS, BATCH);
    attn_kernel<<<attn_grid, 128, ATTN_SMEM>>>(k_out, v_out);

    gemm_tf32_kernel<<<gemm_grid, 256, GEMM_SMEM>>>(ctxptr, wt_o, bo, ao_out, 1.0f, 0);

    ln_kernel<<<NROWS, 256>>>(x, ao_out, gamma, beta, ln_out);
}

// round 4
// speedup vs baseline: 3.6527x; 1.9991x over previous
#include <cuda_runtime.h>
#include <cstdint>

// ---------------------------------------------------------------------------
// Problem constants
// ---------------------------------------------------------------------------
#define BATCH   2
#define SEQ     2048
#define DMODEL  2048
#define NHEADS  16
#define DH      128
#define NROWS   (BATCH*SEQ)              // 4096
#define CHUNK_E ((size_t)NROWS*DMODEL)

// Scratch (__device__ globals: allocation-free rule)
__device__ float g_q  [(size_t)BATCH*NHEADS*SEQ*DH];   // Q [B,H,S,Dh], pre-scaled
__device__ float g_ctx[(size_t)NROWS*DMODEL];          // ctx (tf32-rounded)
__device__ float g_wt [4ULL*DMODEL*DMODEL];            // W^T (tf32-rounded)
__device__ float g_x  [(size_t)NROWS*DMODEL];          // x (tf32-rounded)
__device__ float g_kr [(size_t)BATCH*NHEADS*SEQ*DH];   // K (tf32-rounded)
__device__ float g_vt [(size_t)BATCH*NHEADS*DH*SEQ];   // V^T [B,H,Dh,S] (tf32-rounded)

// ---------------------------------------------------------------------------
// PTX helpers (baseline features only: work under compute_103)
// ---------------------------------------------------------------------------
__device__ __forceinline__ uint32_t smem_u32(const void* p) {
    uint32_t a;
    asm("{ .reg .u64 t; cvta.to.shared.u64 t, %1; cvt.u32.u64 %0, t; }"
        : "=r"(a) : "l"(p));
    return a;
}
__device__ __forceinline__ float tf32r(float x) {
    float r;
    asm("cvt.rna.tf32.f32 %0, %1;" : "=f"(r) : "f"(x));
    return r;
}
#define CP_ASYNC16(dst, src) \
    asm volatile("cp.async.cg.shared.global [%0], [%1], 16;" :: "r"(dst), "l"(src))
#define CP_COMMIT()  asm volatile("cp.async.commit_group;" ::: "memory")
#define CP_WAIT1()   asm volatile("cp.async.wait_group 1;" ::: "memory")
#define CP_WAIT0()   asm volatile("cp.async.wait_group 0;" ::: "memory")

__device__ __forceinline__ void ldsm_x4(uint32_t& r0, uint32_t& r1,
                                        uint32_t& r2, uint32_t& r3, uint32_t a) {
    asm volatile("ldmatrix.sync.aligned.m8n8.x4.shared.b16 {%0,%1,%2,%3}, [%4];"
                 : "=r"(r0), "=r"(r1), "=r"(r2), "=r"(r3) : "r"(a));
}
__device__ __forceinline__ void mma_tf32(float* c, const uint32_t* a,
                                         uint32_t b0, uint32_t b1) {
    asm volatile(
        "mma.sync.aligned.m16n8k8.row.col.f32.tf32.tf32.f32 "
        "{%0,%1,%2,%3},{%4,%5,%6,%7},{%8,%9},{%0,%1,%2,%3};"
        : "+f"(c[0]), "+f"(c[1]), "+f"(c[2]), "+f"(c[3])
        : "r"(a[0]), "r"(a[1]), "r"(a[2]), "r"(a[3]), "r"(b0), "r"(b1));
}

// ---------------------------------------------------------------------------
// tf32-rounded copy
// ---------------------------------------------------------------------------
__global__ __launch_bounds__(256) void round_tf32_kernel(
    const float* __restrict__ in, float* __restrict__ out)
{
    const int i = blockIdx.x * 256 + threadIdx.x;
    float4 v = ((const float4*)in)[i];
    v.x = tf32r(v.x); v.y = tf32r(v.y); v.z = tf32r(v.z); v.w = tf32r(v.w);
    ((float4*)out)[i] = v;
}

// ---------------------------------------------------------------------------
// Weight transpose (+ tf32 rounding): out[n][k] = round(in[k][n])
// ---------------------------------------------------------------------------
__global__ __launch_bounds__(256) void transpose_kernel(
    const float* __restrict__ in, float* __restrict__ out)
{
    __shared__ float t[32][33];
    const int x  = blockIdx.x * 32 + threadIdx.x;
    const int y0 = blockIdx.y * 32 + threadIdx.y;
    #pragma unroll
    for (int j = 0; j < 4; j++)
        t[threadIdx.y + j * 8][threadIdx.x] = in[(size_t)(y0 + j * 8) * DMODEL + x];
    __syncthreads();
    const int x2  = blockIdx.y * 32 + threadIdx.x;
    const int y20 = blockIdx.x * 32 + threadIdx.y;
    #pragma unroll
    for (int j = 0; j < 4; j++)
        out[(size_t)(y20 + j * 8) * DMODEL + x2] =
            tf32r(t[threadIdx.x][threadIdx.y + j * 8]);
}

// ---------------------------------------------------------------------------
// V transpose per head: vt[bh][d][s] = round(v[bh][s][d])
// ---------------------------------------------------------------------------
__global__ __launch_bounds__(256) void vtrans_kernel(
    const float* __restrict__ v, float* __restrict__ vt)
{
    __shared__ float t[32][33];
    const int bh = blockIdx.z;
    const float* in = v + (size_t)bh * SEQ * DH;
    float* out = vt + (size_t)bh * DH * SEQ;
    const int s0 = blockIdx.x * 32, d0 = blockIdx.y * 32;
    #pragma unroll
    for (int j = 0; j < 4; j++)
        t[threadIdx.y + j * 8][threadIdx.x] =
            in[(size_t)(s0 + threadIdx.y + j * 8) * DH + d0 + threadIdx.x];
    __syncthreads();
    #pragma unroll
    for (int j = 0; j < 4; j++)
        out[(size_t)(d0 + threadIdx.y + j * 8) * SEQ + s0 + threadIdx.x] =
            tf32r(t[threadIdx.x][threadIdx.y + j * 8]);
}

// ---------------------------------------------------------------------------
// TF32 mma.sync GEMM (unchanged from round 3, passing)
// ---------------------------------------------------------------------------
#define BK 32
#define NCHUNK (DMODEL / BK)
#define LDS_STRIDE 36
#define TILE_B (128 * LDS_STRIDE * 4)
#define SA0 0
#define SA1 TILE_B
#define SB0 (2 * TILE_B)
#define SB1 (3 * TILE_B)
#define GEMM_SMEM (4 * TILE_B)

__global__ __launch_bounds__(256, 2) void gemm_tf32_kernel(
    const float* __restrict__ A, const float* __restrict__ Bt,
    const float* __restrict__ bias, float* __restrict__ C,
    float scale, int qkv_mode)
{
    extern __shared__ char smc[];
    const uint32_t sb = smem_u32(smc);
    const int tid = threadIdx.x;
    const int wid = tid >> 5, lane = tid & 31;
    const int bx = blockIdx.x, by = blockIdx.y;

    const float* Ab = A  + (size_t)(by * 128) * DMODEL;
    const float* Bb = Bt + (size_t)(bx * 128) * DMODEL;

    const int grow = tid >> 3;
    const int gcol = (tid & 7) * 4;
    auto load_chunk = [&](int chunk, int p) {
        const float* as = Ab + (size_t)grow * DMODEL + chunk * BK + gcol;
        const float* bs = Bb + (size_t)grow * DMODEL + chunk * BK + gcol;
        const uint32_t ad = sb + (p ? SA1 : SA0) + grow * (LDS_STRIDE * 4) + gcol * 4;
        const uint32_t bd = sb + (p ? SB1 : SB0) + grow * (LDS_STRIDE * 4) + gcol * 4;
        #pragma unroll
        for (int r = 0; r < 4; r++) {
            CP_ASYNC16(ad + r * 32 * (LDS_STRIDE * 4), as + (size_t)r * 32 * DMODEL);
            CP_ASYNC16(bd + r * 32 * (LDS_STRIDE * 4), bs + (size_t)r * 32 * DMODEL);
        }
    };

    const int wm = wid & 1;
    const int wn = wid >> 1;
    const int r7  = lane & 7;
    const int sel = lane >> 3;

    uint32_t aAddr[2][4], bAddr[2][2];
    {
        const int arow = wm * 64 + (sel & 1) * 8 + r7;
        const int acol = (sel >> 1) * 4;
        const int brow = wn * 32 + (sel >> 1) * 8 + r7;
        const int bcol = (sel & 1) * 4;
        #pragma unroll
        for (int p = 0; p < 2; p++) {
            #pragma unroll
            for (int mt = 0; mt < 4; mt++)
                aAddr[p][mt] = sb + (p ? SA1 : SA0)
                             + (arow + mt * 16) * (LDS_STRIDE * 4) + acol * 4;
            #pragma unroll
            for (int np = 0; np < 2; np++)
                bAddr[p][np] = sb + (p ? SB1 : SB0)
                             + (brow + np * 16) * (LDS_STRIDE * 4) + bcol * 4;
        }
    }

    float acc[4][4][4];
    #pragma unroll
    for (int mt = 0; mt < 4; mt++)
        #pragma unroll
        for (int nt = 0; nt < 4; nt++)
            #pragma unroll
            for (int q = 0; q < 4; q++) acc[mt][nt][q] = 0.f;

    load_chunk(0, 0); CP_COMMIT();
    load_chunk(1, 1); CP_COMMIT();

    for (int i = 0; i < NCHUNK; i++) {
        const int p = i & 1;
        if (i + 2 < NCHUNK) { CP_WAIT1(); } else { CP_WAIT0(); }
        __syncthreads();

        #pragma unroll
        for (int ks = 0; ks < 4; ks++) {
            uint32_t a[4][4], b[2][4];
            #pragma unroll
            for (int mt = 0; mt < 4; mt++)
                ldsm_x4(a[mt][0], a[mt][1], a[mt][2], a[mt][3],
                        aAddr[p][mt] + ks * 32);
            #pragma unroll
            for (int np = 0; np < 2; np++)
                ldsm_x4(b[np][0], b[np][1], b[np][2], b[np][3],
                        bAddr[p][np] + ks * 32);
            #pragma unroll
            for (int mt = 0; mt < 4; mt++)
                #pragma unroll
                for (int nt = 0; nt < 4; nt++)
                    mma_tf32(acc[mt][nt], a[mt],
                             b[nt >> 1][(nt & 1) * 2], b[nt >> 1][(nt & 1) * 2 + 1]);
        }

        __syncthreads();
        if (i + 2 < NCHUNK) { load_chunk(i + 2, p); CP_COMMIT(); }
    }

    const int qr = lane >> 2;
    const int qc = (lane & 3) * 2;
    #pragma unroll
    for (int nt = 0; nt < 4; nt++) {
        const int dh = wn * 32 + nt * 8 + qc;
        const float bv0 = bias[bx * 128 + dh];
        const float bv1 = bias[bx * 128 + dh + 1];
        #pragma unroll
        for (int mt = 0; mt < 4; mt++) {
            #pragma unroll
            for (int half = 0; half < 2; half++) {
                const int mrow = by * 128 + wm * 64 + mt * 16 + half * 8 + qr;
                float2 r;
                r.x = (acc[mt][nt][half * 2 + 0] + bv0) * scale;
                r.y = (acc[mt][nt][half * 2 + 1] + bv1) * scale;
                float* dst;
                if (qkv_mode == 0) {
                    dst = C + (size_t)mrow * DMODEL + bx * 128 + dh;
                } else {
                    const int b = mrow >> 11, s = mrow & 2047;
                    dst = C + (((size_t)(b * NHEADS + bx) * SEQ + s) * DH) + dh;
                }
                *(float2*)dst = r;
            }
        }
    }
}

// ---------------------------------------------------------------------------
// Tensor-core causal flash attention.
//   Block: 256 thr (8 warps), 128 q-rows per CTA, BJ=64 key tile.
//   Warp w owns q rows [w*16, w*16+16): S = Q K^T via mma, in-register online
//   softmax, P staged through warp-private smem -> ldmatrix -> P V via mma.
//   Q fragments persist in registers; K and V^T double-buffered via cp.async.
// ---------------------------------------------------------------------------
#define BQ 128
#define BJ 64
#define KS_ST 132                           // floats (528 B rows)
#define VT_ST 68                            // floats (272 B rows)
#define PS_ST 72                            // floats (288 B rows)
#define SK_OFF(p) ((p) * (BJ * KS_ST * 4))
#define SV_OFF(p) (2 * (BJ * KS_ST * 4) + (p) * (DH * VT_ST * 4))
#define PS_OFF    (2 * (BJ * KS_ST * 4) + 2 * (DH * VT_ST * 4))
#define ATTN2_SMEM (PS_OFF + BQ * PS_ST * 4)   // 174080 B

__global__ __launch_bounds__(256, 1) void attn_tc_kernel(
    const float* __restrict__ Kr, const float* __restrict__ Vt)
{
    extern __shared__ char smc[];
    const uint32_t sb = smem_u32(smc);
    const int tid = threadIdx.x, wid = tid >> 5, lane = tid & 31;
    const int qb = blockIdx.x, h = blockIdx.y, b = blockIdx.z;
    const int q0 = qb * BQ;
    const int wq = wid * 16;
    const int r7 = lane & 7, sel = lane >> 3;
    const int qr = lane >> 2, qc2 = (lane & 3) * 2;

    const size_t headoff = (size_t)(b * NHEADS + h) * SEQ * DH;
    const float* qbase  = g_q + headoff;
    const float* kbase  = Kr  + headoff;
    const float* vtbase = Vt  + (size_t)(b * NHEADS + h) * DH * SEQ;

    // ---- stage Q (tf32-rounded) and load persistent A fragments ----
    #pragma unroll
    for (int i = 0; i < 16; i++) {
        const int idx = i * 256 + tid;
        const int row = idx >> 5, c4 = idx & 31;
        float4 v = *(const float4*)(qbase + (size_t)(q0 + row) * DH + c4 * 4);
        v.x = tf32r(v.x); v.y = tf32r(v.y); v.z = tf32r(v.z); v.w = tf32r(v.w);
        *(float4*)(smc + row * (KS_ST * 4) + c4 * 16) = v;
    }
    __syncthreads();
    uint32_t qf[16][4];
    {
        const uint32_t ab = sb + (wq + (sel & 1) * 8 + r7) * (KS_ST * 4)
                          + (sel >> 1) * 16;
        #pragma unroll
        for (int kt = 0; kt < 16; kt++)
            ldsm_x4(qf[kt][0], qf[kt][1], qf[kt][2], qf[kt][3], ab + kt * 32);
    }
    __syncthreads();

    auto prefetch = [&](int t, int p) {
        const int j0 = t * BJ;
        {   // K tile: 64 rows x 128 floats
            const float* src = kbase + (size_t)(j0 + (tid >> 2)) * DH + (tid & 3) * 32;
            const uint32_t dst = sb + SK_OFF(p) + (tid >> 2) * (KS_ST * 4) + (tid & 3) * 128;
            #pragma unroll
            for (int i = 0; i < 8; i++) CP_ASYNC16(dst + i * 16, src + i * 4);
        }
        {   // V^T tile: 128 rows x 64 floats
            const float* src = vtbase + (size_t)(tid >> 1) * SEQ + j0 + (tid & 1) * 32;
            const uint32_t dst = sb + SV_OFF(p) + (tid >> 1) * (VT_ST * 4) + (tid & 1) * 128;
            #pragma unroll
            for (int i = 0; i < 8; i++) CP_ASYNC16(dst + i * 16, src + i * 4);
        }
    };

    float oacc[16][4];
    #pragma unroll
    for (int nt = 0; nt < 16; nt++)
        #pragma unroll
        for (int q = 0; q < 4; q++) oacc[nt][q] = 0.f;
    float m[2] = {-1e30f, -1e30f}, l[2] = {0.f, 0.f};

    const int ntiles = 2 * qb + 2;
    prefetch(0, 0); CP_COMMIT();

    for (int t = 0; t < ntiles; t++) {
        const int p = t & 1;
        __syncthreads();                         // compute t-1 done with buf 1-p
        if (t + 1 < ntiles) { prefetch(t + 1, 1 - p); CP_COMMIT(); CP_WAIT1(); }
        else                { CP_WAIT0(); }
        __syncthreads();                         // tile t visible to all warps

        const int j0 = t * BJ;
        if (j0 > q0 + wq + 15) continue;         // warp fully masked

        // ---- S = Q K^T ----
        float sacc[8][4];
        #pragma unroll
        for (int nt = 0; nt < 8; nt++)
            #pragma unroll
            for (int q = 0; q < 4; q++) sacc[nt][q] = 0.f;

        const uint32_t kb0 = sb + SK_OFF(p)
                           + ((sel >> 1) * 8 + r7) * (KS_ST * 4) + (sel & 1) * 16;
        #pragma unroll
        for (int kt = 0; kt < 16; kt++) {
            #pragma unroll
            for (int np = 0; np < 4; np++) {
                uint32_t b0, b1, b2, b3;
                ldsm_x4(b0, b1, b2, b3, kb0 + np * 16 * (KS_ST * 4) + kt * 32);
                mma_tf32(sacc[2 * np],     qf[kt], b0, b1);
                mma_tf32(sacc[2 * np + 1], qf[kt], b2, b3);
            }
        }

        // ---- causal mask ----
        const int row0 = q0 + wq + qr;
        if (j0 + BJ - 1 > q0 + wq) {
            #pragma unroll
            for (int nt = 0; nt < 8; nt++) {
                const int c0 = j0 + nt * 8 + qc2;
                if (c0     > row0)     sacc[nt][0] = -1e30f;
                if (c0 + 1 > row0)     sacc[nt][1] = -1e30f;
                if (c0     > row0 + 8) sacc[nt][2] = -1e30f;
                if (c0 + 1 > row0 + 8) sacc[nt][3] = -1e30f;
            }
        }

        // ---- online softmax (2 rows per thread) ----
        #pragma unroll
        for (int r = 0; r < 2; r++) {
            float rmax = -1e30f;
            #pragma unroll
            for (int nt = 0; nt < 8; nt++)
                rmax = fmaxf(rmax, fmaxf(sacc[nt][2 * r], sacc[nt][2 * r + 1]));
            rmax = fmaxf(rmax, __shfl_xor_sync(0xffffffffu, rmax, 1));
            rmax = fmaxf(rmax, __shfl_xor_sync(0xffffffffu, rmax, 2));
            const float mnew  = fmaxf(m[r], rmax);
            const float alpha = __expf(m[r] - mnew);
            float rsum = 0.f;
            #pragma unroll
            for (int nt = 0; nt < 8; nt++) {
                float p0 = __expf(sacc[nt][2 * r]     - mnew);
                float p1 = __expf(sacc[nt][2 * r + 1] - mnew);
                sacc[nt][2 * r] = p0; sacc[nt][2 * r + 1] = p1;
                rsum += p0 + p1;
            }
            rsum += __shfl_xor_sync(0xffffffffu, rsum, 1);
            rsum += __shfl_xor_sync(0xffffffffu, rsum, 2);
            l[r] = l[r] * alpha + rsum;
            m[r] = mnew;
            #pragma unroll
            for (int nt = 0; nt < 16; nt++) {
                oacc[nt][2 * r]     *= alpha;
                oacc[nt][2 * r + 1] *= alpha;
            }
        }

        // ---- stage P (tf32-rounded) to warp-private smem ----
        {
            const uint32_t pbo = PS_OFF + (wq + qr) * (PS_ST * 4) + qc2 * 4;
            #pragma unroll
            for (int nt = 0; nt < 8; nt++) {
                float2 v0 = make_float2(tf32r(sacc[nt][0]), tf32r(sacc[nt][1]));
                float2 v1 = make_float2(tf32r(sacc[nt][2]), tf32r(sacc[nt][3]));
                *(float2*)(smc + pbo + nt * 32)                    = v0;
                *(float2*)(smc + pbo + 8 * (PS_ST * 4) + nt * 32)  = v1;
            }
        }
        __syncwarp();

        // ---- O += P V ----
        const uint32_t pab = sb + PS_OFF
                           + (wq + (sel & 1) * 8 + r7) * (PS_ST * 4) + (sel >> 1) * 16;
        const uint32_t vb0 = sb + SV_OFF(p)
                           + ((sel >> 1) * 8 + r7) * (VT_ST * 4) + (sel & 1) * 16;
        #pragma unroll
        for (int kt = 0; kt < 8; kt++) {
            uint32_t pa[4];
            ldsm_x4(pa[0], pa[1], pa[2], pa[3], pab + kt * 32);
            #pragma unroll
            for (int np = 0; np < 8; np++) {
                uint32_t b0, b1, b2, b3;
                ldsm_x4(b0, b1, b2, b3, vb0 + np * 16 * (VT_ST * 4) + kt * 32);
                mma_tf32(oacc[2 * np],     pa, b0, b1);
                mma_tf32(oacc[2 * np + 1], pa, b2, b3);
            }
        }
    }

    // ---- epilogue: O /= l, write ctx (tf32-rounded, feeds o-GEMM) ----
    const float inv0 = 1.f / l[0], inv1 = 1.f / l[1];
    float* crow0 = g_ctx + (size_t)(b * SEQ + q0 + wq + qr) * DMODEL + h * DH + qc2;
    float* crow1 = crow0 + 8 * DMODEL;
    #pragma unroll
    for (int nt = 0; nt < 16; nt++) {
        float2 v0 = make_float2(tf32r(oacc[nt][0] * inv0), tf32r(oacc[nt][1] * inv0));
        float2 v1 = make_float2(tf32r(oacc[nt][2] * inv1), tf32r(oacc[nt][3] * inv1));
        *(float2*)(crow0 + nt * 8) = v0;
        *(float2*)(crow1 + nt * 8) = v1;
    }
}

// ---------------------------------------------------------------------------
// Residual + LayerNorm
// ---------------------------------------------------------------------------
__global__ __launch_bounds__(256) void ln_kernel(
    const float* __restrict__ x, const float* __restrict__ ao,
    const float* __restrict__ gamma, const float* __restrict__ beta,
    float* __restrict__ out)
{
    __shared__ float ys[DMODEL];
    __shared__ float s_part[16];
    __shared__ float s_mu, s_rstd;

    const int r = blockIdx.x;
    const int t = threadIdx.x;
    const float* xr = x + (size_t)r * DMODEL;
    const float* ar = ao + (size_t)r * DMODEL;

    float sum = 0.f, sq = 0.f;
    for (int d = t; d < DMODEL; d += 256) {
        float y = xr[d] + ar[d];
        ys[d] = y;
        sum += y;
        sq  += y * y;
    }
    #pragma unroll
    for (int off = 16; off > 0; off >>= 1) {
        sum += __shfl_xor_sync(0xffffffffu, sum, off);
        sq  += __shfl_xor_sync(0xffffffffu, sq, off);
    }
    const int wid = t >> 5, lane = t & 31;
    if (lane == 0) { s_part[wid] = sum; s_part[8 + wid] = sq; }
    __syncthreads();
    if (t == 0) {
        float S = 0.f, Q = 0.f;
        #pragma unroll
        for (int w = 0; w < 8; w++) { S += s_part[w]; Q += s_part[8 + w]; }
        float mu  = S * (1.f / DMODEL);
        float var = Q * (1.f / DMODEL) - mu * mu;
        s_mu = mu;
        s_rstd = rsqrtf(var + 1e-5f);
    }
    __syncthreads();
    const float mu = s_mu, rstd = s_rstd;
    float* outr = out + (size_t)r * DMODEL;
    for (int d = t; d < DMODEL; d += 256)
        outr[d] = gamma[d] * (ys[d] - mu) * rstd + beta[d];
}

// ---------------------------------------------------------------------------
extern "C" void kernel_launch(void* const* d_in, const int* in_sizes, int n_in,
                              void* d_out, int out_size)
{
    const float* x     = (const float*)d_in[0];
    const float* Wq    = (const float*)d_in[1];
    const float* bq    = (const float*)d_in[2];
    const float* Wk    = (const float*)d_in[3];
    const float* bk    = (const float*)d_in[4];
    const float* Wv    = (const float*)d_in[5];
    const float* bv    = (const float*)d_in[6];
    const float* Wo    = (const float*)d_in[7];
    const float* bo    = (const float*)d_in[8];
    const float* gamma = (const float*)d_in[9];
    const float* beta  = (const float*)d_in[10];

    float* out    = (float*)d_out;
    float* ln_out = out;
    float* ao_out = out + CHUNK_E;
    float* k_out  = out + 2 * CHUNK_E;   // [B,H,S,Dh]
    float* v_out  = out + 3 * CHUNK_E;   // [B,H,S,Dh]

    float *qptr = nullptr, *ctxptr = nullptr, *wtptr = nullptr, *xptr = nullptr;
    float *krptr = nullptr, *vtptr = nullptr;
    cudaGetSymbolAddress((void**)&qptr,   g_q);
    cudaGetSymbolAddress((void**)&ctxptr, g_ctx);
    cudaGetSymbolAddress((void**)&wtptr,  g_wt);
    cudaGetSymbolAddress((void**)&xptr,   g_x);
    cudaGetSymbolAddress((void**)&krptr,  g_kr);
    cudaGetSymbolAddress((void**)&vtptr,  g_vt);
    float* wt_q = wtptr;
    float* wt_k = wtptr + 1ULL * DMODEL * DMODEL;
    float* wt_v = wtptr + 2ULL * DMODEL * DMODEL;
    float* wt_o = wtptr + 3ULL * DMODEL * DMODEL;

    cudaFuncSetAttribute(gemm_tf32_kernel,
                         cudaFuncAttributeMaxDynamicSharedMemorySize, GEMM_SMEM);
    cudaFuncSetAttribute(attn_tc_kernel,
                         cudaFuncAttributeMaxDynamicSharedMemorySize, ATTN2_SMEM);

    // Pre-round x and W^T to tf32
    round_tf32_kernel<<<(int)(CHUNK_E / 4 / 256), 256>>>(x, xptr);
    dim3 tg(DMODEL / 32, DMODEL / 32), tb(32, 8);
    transpose_kernel<<<tg, tb>>>(Wq, wt_q);
    transpose_kernel<<<tg, tb>>>(Wk, wt_k);
    transpose_kernel<<<tg, tb>>>(Wv, wt_v);
    transpose_kernel<<<tg, tb>>>(Wo, wt_o);

    const float qscale = 0.08838834764831845f;  // 1/sqrt(128)
    dim3 gemm_grid(DMODEL / 128, NROWS / 128);

    gemm_tf32_kernel<<<gemm_grid, 256, GEMM_SMEM>>>(xptr, wt_q, bq, qptr,  qscale, 1);
    gemm_tf32_kernel<<<gemm_grid, 256, GEMM_SMEM>>>(xptr, wt_k, bk, k_out, 1.0f,   1);
    gemm_tf32_kernel<<<gemm_grid, 256, GEMM_SMEM>>>(xptr, wt_v, bv, v_out, 1.0f,   1);

    // tf32-rounded K copy + per-head V transpose (attention operands)
    round_tf32_kernel<<<(int)(CHUNK_E / 4 / 256), 256>>>(k_out, krptr);
    dim3 vg(SEQ / 32, DH / 32, BATCH * NHEADS), vb2(32, 8);
    vtrans_kernel<<<vg, vb2>>>(v_out, vtptr);

    dim3 attn_grid(SEQ / BQ, NHEADS, BATCH);
    attn_tc_kernel<<<attn_grid, 256, ATTN2_SMEM>>>(krptr, vtptr);

    gemm_tf32_kernel<<<gemm_grid, 256, GEMM_SMEM>>>(ctxptr, wt_o, bo, ao_out, 1.0f, 0);

    ln_kernel<<<NROWS, 256>>>(x, ao_out, gamma, beta, ln_out);
}

// round 5
// speedup vs baseline: 3.7183x; 1.0180x over previous
#include <cuda_runtime.h>
#include <cstdint>

// ---------------------------------------------------------------------------
// Problem constants
// ---------------------------------------------------------------------------
#define BATCH   2
#define SEQ     2048
#define DMODEL  2048
#define NHEADS  16
#define DH      128
#define NROWS   (BATCH*SEQ)              // 4096
#define CHUNK_E ((size_t)NROWS*DMODEL)

// Scratch (__device__ globals: allocation-free rule)
__device__ float g_q  [(size_t)BATCH*NHEADS*SEQ*DH];   // Q [B,H,S,Dh], pre-scaled
__device__ float g_ctx[(size_t)NROWS*DMODEL];          // ctx (tf32-rounded)
__device__ float g_wt [4ULL*DMODEL*DMODEL];            // W^T (tf32-rounded)
__device__ float g_x  [(size_t)NROWS*DMODEL];          // x (tf32-rounded)
__device__ float g_kr [(size_t)BATCH*NHEADS*SEQ*DH];   // K (tf32-rounded)
__device__ float g_vt [(size_t)BATCH*NHEADS*DH*SEQ];   // V^T [B,H,Dh,S] (tf32-rounded)

// ---------------------------------------------------------------------------
// PTX helpers (baseline features only: work under compute_103)
// ---------------------------------------------------------------------------
__device__ __forceinline__ uint32_t smem_u32(const void* p) {
    uint32_t a;
    asm("{ .reg .u64 t; cvta.to.shared.u64 t, %1; cvt.u32.u64 %0, t; }"
        : "=r"(a) : "l"(p));
    return a;
}
__device__ __forceinline__ float tf32r(float x) {
    float r;
    asm("cvt.rna.tf32.f32 %0, %1;" : "=f"(r) : "f"(x));
    return r;
}
#define CP_ASYNC16(dst, src) \
    asm volatile("cp.async.cg.shared.global [%0], [%1], 16;" :: "r"(dst), "l"(src))
#define CP_COMMIT()  asm volatile("cp.async.commit_group;" ::: "memory")
#define CP_WAIT1()   asm volatile("cp.async.wait_group 1;" ::: "memory")
#define CP_WAIT0()   asm volatile("cp.async.wait_group 0;" ::: "memory")

__device__ __forceinline__ void ldsm_x4(uint32_t& r0, uint32_t& r1,
                                        uint32_t& r2, uint32_t& r3, uint32_t a) {
    asm volatile("ldmatrix.sync.aligned.m8n8.x4.shared.b16 {%0,%1,%2,%3}, [%4];"
                 : "=r"(r0), "=r"(r1), "=r"(r2), "=r"(r3) : "r"(a));
}
__device__ __forceinline__ void mma_tf32(float* c, const uint32_t* a,
                                         uint32_t b0, uint32_t b1) {
    asm volatile(
        "mma.sync.aligned.m16n8k8.row.col.f32.tf32.tf32.f32 "
        "{%0,%1,%2,%3},{%4,%5,%6,%7},{%8,%9},{%0,%1,%2,%3};"
        : "+f"(c[0]), "+f"(c[1]), "+f"(c[2]), "+f"(c[3])
        : "r"(a[0]), "r"(a[1]), "r"(a[2]), "r"(a[3]), "r"(b0), "r"(b1));
}

// ---------------------------------------------------------------------------
// tf32-rounded copy
// ---------------------------------------------------------------------------
__global__ __launch_bounds__(256) void round_tf32_kernel(
    const float* __restrict__ in, float* __restrict__ out)
{
    const int i = blockIdx.x * 256 + threadIdx.x;
    float4 v = ((const float4*)in)[i];
    v.x = tf32r(v.x); v.y = tf32r(v.y); v.z = tf32r(v.z); v.w = tf32r(v.w);
    ((float4*)out)[i] = v;
}

// ---------------------------------------------------------------------------
// Weight transpose (+ tf32 rounding): out[n][k] = round(in[k][n])
// ---------------------------------------------------------------------------
__global__ __launch_bounds__(256) void transpose_kernel(
    const float* __restrict__ in, float* __restrict__ out)
{
    __shared__ float t[32][33];
    const int x  = blockIdx.x * 32 + threadIdx.x;
    const int y0 = blockIdx.y * 32 + threadIdx.y;
    #pragma unroll
    for (int j = 0; j < 4; j++)
        t[threadIdx.y + j * 8][threadIdx.x] = in[(size_t)(y0 + j * 8) * DMODEL + x];
    __syncthreads();
    const int x2  = blockIdx.y * 32 + threadIdx.x;
    const int y20 = blockIdx.x * 32 + threadIdx.y;
    #pragma unroll
    for (int j = 0; j < 4; j++)
        out[(size_t)(y20 + j * 8) * DMODEL + x2] =
            tf32r(t[threadIdx.x][threadIdx.y + j * 8]);
}

// ---------------------------------------------------------------------------
// V transpose per head: vt[bh][d][s] = round(v[bh][s][d])
// ---------------------------------------------------------------------------
__global__ __launch_bounds__(256) void vtrans_kernel(
    const float* __restrict__ v, float* __restrict__ vt)
{
    __shared__ float t[32][33];
    const int bh = blockIdx.z;
    const float* in = v + (size_t)bh * SEQ * DH;
    float* out = vt + (size_t)bh * DH * SEQ;
    const int s0 = blockIdx.x * 32, d0 = blockIdx.y * 32;
    #pragma unroll
    for (int j = 0; j < 4; j++)
        t[threadIdx.y + j * 8][threadIdx.x] =
            in[(size_t)(s0 + threadIdx.y + j * 8) * DH + d0 + threadIdx.x];
    __syncthreads();
    #pragma unroll
    for (int j = 0; j < 4; j++)
        out[(size_t)(d0 + threadIdx.y + j * 8) * SEQ + s0 + threadIdx.x] =
            tf32r(t[threadIdx.x][threadIdx.y + j * 8]);
}

// ---------------------------------------------------------------------------
// TF32 mma.sync GEMM, 3-stage cp.async pipeline.
//   C = scale * (A[4096,2048] @ Bt^T + bias); optional C2 = tf32r(C) (mode 1).
//   128x128 CTA tile, BK=32, 8 warps of 64x32, one __syncthreads per chunk.
// ---------------------------------------------------------------------------
#define BK 32
#define NCHUNK (DMODEL / BK)          // 64
#define LDS_STRIDE 36
#define ROWB (LDS_STRIDE * 4)
#define TILE_B (128 * ROWB)           // 18432 bytes per tile buffer
#define GEMM_SMEM (6 * TILE_B)        // 110592: A stages [0,3), B stages [3,6)

__global__ __launch_bounds__(256, 2) void gemm_tf32_kernel(
    const float* __restrict__ A, const float* __restrict__ Bt,
    const float* __restrict__ bias, float* __restrict__ C,
    float* __restrict__ C2,           // optional tf32-rounded copy (mode 1)
    float scale, int qkv_mode)
{
    extern __shared__ char smc[];
    const uint32_t sb = smem_u32(smc);
    const int tid = threadIdx.x;
    const int wid = tid >> 5, lane = tid & 31;
    const int bx = blockIdx.x, by = blockIdx.y;

    const float* Ab = A  + (size_t)(by * 128) * DMODEL;
    const float* Bb = Bt + (size_t)(bx * 128) * DMODEL;

    const int grow = tid >> 3;
    const int gcol = (tid & 7) * 4;
    auto load_chunk = [&](int chunk, int p) {
        const float* as = Ab + (size_t)grow * DMODEL + chunk * BK + gcol;
        const float* bs = Bb + (size_t)grow * DMODEL + chunk * BK + gcol;
        const uint32_t ad = sb + p * TILE_B              + grow * ROWB + gcol * 4;
        const uint32_t bd = sb + (3 + p) * TILE_B        + grow * ROWB + gcol * 4;
        #pragma unroll
        for (int r = 0; r < 4; r++) {
            CP_ASYNC16(ad + r * 32 * ROWB, as + (size_t)r * 32 * DMODEL);
            CP_ASYNC16(bd + r * 32 * ROWB, bs + (size_t)r * 32 * DMODEL);
        }
    };

    const int wm = wid & 1;
    const int wn = wid >> 1;
    const int r7  = lane & 7;
    const int sel = lane >> 3;

    // per-thread constant ldmatrix offsets (stage base added per iter)
    const uint32_t aoff = (uint32_t)((wm * 64 + (sel & 1) * 8 + r7) * ROWB
                                   + (sel >> 1) * 16);
    const uint32_t boff = (uint32_t)((wn * 32 + (sel >> 1) * 8 + r7) * ROWB
                                   + (sel & 1) * 16);

    float acc[4][4][4];
    #pragma unroll
    for (int mt = 0; mt < 4; mt++)
        #pragma unroll
        for (int nt = 0; nt < 4; nt++)
            #pragma unroll
            for (int q = 0; q < 4; q++) acc[mt][nt][q] = 0.f;

    load_chunk(0, 0); CP_COMMIT();
    load_chunk(1, 1); CP_COMMIT();

    int p = 0;   // stage of chunk i
    for (int i = 0; i < NCHUNK; i++) {
        if (i < NCHUNK - 1) { CP_WAIT1(); } else { CP_WAIT0(); }
        __syncthreads();
        if (i + 2 < NCHUNK) {
            int pn = p + 2; if (pn >= 3) pn -= 3;
            load_chunk(i + 2, pn);
            CP_COMMIT();
        }

        const uint32_t sa  = sb + p * TILE_B + aoff;
        const uint32_t sbb = sb + (3 + p) * TILE_B + boff;
        #pragma unroll
        for (int ks = 0; ks < 4; ks++) {
            uint32_t a[4][4], b[2][4];
            #pragma unroll
            for (int mt = 0; mt < 4; mt++)
                ldsm_x4(a[mt][0], a[mt][1], a[mt][2], a[mt][3],
                        sa + mt * 16 * ROWB + ks * 32);
            #pragma unroll
            for (int np = 0; np < 2; np++)
                ldsm_x4(b[np][0], b[np][1], b[np][2], b[np][3],
                        sbb + np * 16 * ROWB + ks * 32);
            #pragma unroll
            for (int mt = 0; mt < 4; mt++)
                #pragma unroll
                for (int nt = 0; nt < 4; nt++)
                    mma_tf32(acc[mt][nt], a[mt],
                             b[nt >> 1][(nt & 1) * 2], b[nt >> 1][(nt & 1) * 2 + 1]);
        }
        if (++p == 3) p = 0;
    }

    const int qr = lane >> 2;
    const int qc = (lane & 3) * 2;
    #pragma unroll
    for (int nt = 0; nt < 4; nt++) {
        const int dh = wn * 32 + nt * 8 + qc;
        const float bv0 = bias[bx * 128 + dh];
        const float bv1 = bias[bx * 128 + dh + 1];
        #pragma unroll
        for (int mt = 0; mt < 4; mt++) {
            #pragma unroll
            for (int half = 0; half < 2; half++) {
                const int mrow = by * 128 + wm * 64 + mt * 16 + half * 8 + qr;
                float2 r;
                r.x = (acc[mt][nt][half * 2 + 0] + bv0) * scale;
                r.y = (acc[mt][nt][half * 2 + 1] + bv1) * scale;
                if (qkv_mode == 0) {
                    *(float2*)(C + (size_t)mrow * DMODEL + bx * 128 + dh) = r;
                } else {
                    const int b = mrow >> 11, s = mrow & 2047;
                    const size_t idx = (((size_t)(b * NHEADS + bx) * SEQ + s) * DH) + dh;
                    *(float2*)(C + idx) = r;
                    if (C2) {
                        float2 r2 = make_float2(tf32r(r.x), tf32r(r.y));
                        *(float2*)(C2 + idx) = r2;
                    }
                }
            }
        }
    }
}

// ---------------------------------------------------------------------------
// Tensor-core causal flash attention (unchanged from round 4, passing)
// ---------------------------------------------------------------------------
#define BQ 128
#define BJ 64
#define KS_ST 132
#define VT_ST 68
#define PS_ST 72
#define SK_OFF(p) ((p) * (BJ * KS_ST * 4))
#define SV_OFF(p) (2 * (BJ * KS_ST * 4) + (p) * (DH * VT_ST * 4))
#define PS_OFF    (2 * (BJ * KS_ST * 4) + 2 * (DH * VT_ST * 4))
#define ATTN2_SMEM (PS_OFF + BQ * PS_ST * 4)

__global__ __launch_bounds__(256, 1) void attn_tc_kernel(
    const float* __restrict__ Kr, const float* __restrict__ Vt)
{
    extern __shared__ char smc[];
    const uint32_t sb = smem_u32(smc);
    const int tid = threadIdx.x, wid = tid >> 5, lane = tid & 31;
    const int qb = blockIdx.x, h = blockIdx.y, b = blockIdx.z;
    const int q0 = qb * BQ;
    const int wq = wid * 16;
    const int r7 = lane & 7, sel = lane >> 3;
    const int qr = lane >> 2, qc2 = (lane & 3) * 2;

    const size_t headoff = (size_t)(b * NHEADS + h) * SEQ * DH;
    const float* qbase  = g_q + headoff;
    const float* kbase  = Kr  + headoff;
    const float* vtbase = Vt  + (size_t)(b * NHEADS + h) * DH * SEQ;

    #pragma unroll
    for (int i = 0; i < 16; i++) {
        const int idx = i * 256 + tid;
        const int row = idx >> 5, c4 = idx & 31;
        float4 v = *(const float4*)(qbase + (size_t)(q0 + row) * DH + c4 * 4);
        v.x = tf32r(v.x); v.y = tf32r(v.y); v.z = tf32r(v.z); v.w = tf32r(v.w);
        *(float4*)(smc + row * (KS_ST * 4) + c4 * 16) = v;
    }
    __syncthreads();
    uint32_t qf[16][4];
    {
        const uint32_t ab = sb + (wq + (sel & 1) * 8 + r7) * (KS_ST * 4)
                          + (sel >> 1) * 16;
        #pragma unroll
        for (int kt = 0; kt < 16; kt++)
            ldsm_x4(qf[kt][0], qf[kt][1], qf[kt][2], qf[kt][3], ab + kt * 32);
    }
    __syncthreads();

    auto prefetch = [&](int t, int p) {
        const int j0 = t * BJ;
        {
            const float* src = kbase + (size_t)(j0 + (tid >> 2)) * DH + (tid & 3) * 32;
            const uint32_t dst = sb + SK_OFF(p) + (tid >> 2) * (KS_ST * 4) + (tid & 3) * 128;
            #pragma unroll
            for (int i = 0; i < 8; i++) CP_ASYNC16(dst + i * 16, src + i * 4);
        }
        {
            const float* src = vtbase + (size_t)(tid >> 1) * SEQ + j0 + (tid & 1) * 32;
            const uint32_t dst = sb + SV_OFF(p) + (tid >> 1) * (VT_ST * 4) + (tid & 1) * 128;
            #pragma unroll
            for (int i = 0; i < 8; i++) CP_ASYNC16(dst + i * 16, src + i * 4);
        }
    };

    float oacc[16][4];
    #pragma unroll
    for (int nt = 0; nt < 16; nt++)
        #pragma unroll
        for (int q = 0; q < 4; q++) oacc[nt][q] = 0.f;
    float m[2] = {-1e30f, -1e30f}, l[2] = {0.f, 0.f};

    const int ntiles = 2 * qb + 2;
    prefetch(0, 0); CP_COMMIT();

    for (int t = 0; t < ntiles; t++) {
        const int p = t & 1;
        __syncthreads();
        if (t + 1 < ntiles) { prefetch(t + 1, 1 - p); CP_COMMIT(); CP_WAIT1(); }
        else                { CP_WAIT0(); }
        __syncthreads();

        const int j0 = t * BJ;
        if (j0 > q0 + wq + 15) continue;

        float sacc[8][4];
        #pragma unroll
        for (int nt = 0; nt < 8; nt++)
            #pragma unroll
            for (int q = 0; q < 4; q++) sacc[nt][q] = 0.f;

        const uint32_t kb0 = sb + SK_OFF(p)
                           + ((sel >> 1) * 8 + r7) * (KS_ST * 4) + (sel & 1) * 16;
        #pragma unroll
        for (int kt = 0; kt < 16; kt++) {
            #pragma unroll
            for (int np = 0; np < 4; np++) {
                uint32_t b0, b1, b2, b3;
                ldsm_x4(b0, b1, b2, b3, kb0 + np * 16 * (KS_ST * 4) + kt * 32);
                mma_tf32(sacc[2 * np],     qf[kt], b0, b1);
                mma_tf32(sacc[2 * np + 1], qf[kt], b2, b3);
            }
        }

        const int row0 = q0 + wq + qr;
        if (j0 + BJ - 1 > q0 + wq) {
            #pragma unroll
            for (int nt = 0; nt < 8; nt++) {
                const int c0 = j0 + nt * 8 + qc2;
                if (c0     > row0)     sacc[nt][0] = -1e30f;
                if (c0 + 1 > row0)     sacc[nt][1] = -1e30f;
                if (c0     > row0 + 8) sacc[nt][2] = -1e30f;
                if (c0 + 1 > row0 + 8) sacc[nt][3] = -1e30f;
            }
        }

        #pragma unroll
        for (int r = 0; r < 2; r++) {
            float rmax = -1e30f;
            #pragma unroll
            for (int nt = 0; nt < 8; nt++)
                rmax = fmaxf(rmax, fmaxf(sacc[nt][2 * r], sacc[nt][2 * r + 1]));
            rmax = fmaxf(rmax, __shfl_xor_sync(0xffffffffu, rmax, 1));
            rmax = fmaxf(rmax, __shfl_xor_sync(0xffffffffu, rmax, 2));
            const float mnew  = fmaxf(m[r], rmax);
            const float alpha = __expf(m[r] - mnew);
            float rsum = 0.f;
            #pragma unroll
            for (int nt = 0; nt < 8; nt++) {
                float p0 = __expf(sacc[nt][2 * r]     - mnew);
                float p1 = __expf(sacc[nt][2 * r + 1] - mnew);
                sacc[nt][2 * r] = p0; sacc[nt][2 * r + 1] = p1;
                rsum += p0 + p1;
            }
            rsum += __shfl_xor_sync(0xffffffffu, rsum, 1);
            rsum += __shfl_xor_sync(0xffffffffu, rsum, 2);
            l[r] = l[r] * alpha + rsum;
            m[r] = mnew;
            #pragma unroll
            for (int nt = 0; nt < 16; nt++) {
                oacc[nt][2 * r]     *= alpha;
                oacc[nt][2 * r + 1] *= alpha;
            }
        }

        {
            const uint32_t pbo = PS_OFF + (wq + qr) * (PS_ST * 4) + qc2 * 4;
            #pragma unroll
            for (int nt = 0; nt < 8; nt++) {
                float2 v0 = make_float2(tf32r(sacc[nt][0]), tf32r(sacc[nt][1]));
                float2 v1 = make_float2(tf32r(sacc[nt][2]), tf32r(sacc[nt][3]));
                *(float2*)(smc + pbo + nt * 32)                    = v0;
                *(float2*)(smc + pbo + 8 * (PS_ST * 4) + nt * 32)  = v1;
            }
        }
        __syncwarp();

        const uint32_t pab = sb + PS_OFF
                           + (wq + (sel & 1) * 8 + r7) * (PS_ST * 4) + (sel >> 1) * 16;
        const uint32_t vb0 = sb + SV_OFF(p)
                           + ((sel >> 1) * 8 + r7) * (VT_ST * 4) + (sel & 1) * 16;
        #pragma unroll
        for (int kt = 0; kt < 8; kt++) {
            uint32_t pa[4];
            ldsm_x4(pa[0], pa[1], pa[2], pa[3], pab + kt * 32);
            #pragma unroll
            for (int np = 0; np < 8; np++) {
                uint32_t b0, b1, b2, b3;
                ldsm_x4(b0, b1, b2, b3, vb0 + np * 16 * (VT_ST * 4) + kt * 32);
                mma_tf32(oacc[2 * np],     pa, b0, b1);
                mma_tf32(oacc[2 * np + 1], pa, b2, b3);
            }
        }
    }

    const float inv0 = 1.f / l[0], inv1 = 1.f / l[1];
    float* crow0 = g_ctx + (size_t)(b * SEQ + q0 + wq + qr) * DMODEL + h * DH + qc2;
    float* crow1 = crow0 + 8 * DMODEL;
    #pragma unroll
    for (int nt = 0; nt < 16; nt++) {
        float2 v0 = make_float2(tf32r(oacc[nt][0] * inv0), tf32r(oacc[nt][1] * inv0));
        float2 v1 = make_float2(tf32r(oacc[nt][2] * inv1), tf32r(oacc[nt][3] * inv1));
        *(float2*)(crow0 + nt * 8) = v0;
        *(float2*)(crow1 + nt * 8) = v1;
    }
}

// ---------------------------------------------------------------------------
// Residual + LayerNorm
// ---------------------------------------------------------------------------
__global__ __launch_bounds__(256) void ln_kernel(
    const float* __restrict__ x, const float* __restrict__ ao,
    const float* __restrict__ gamma, const float* __restrict__ beta,
    float* __restrict__ out)
{
    __shared__ float ys[DMODEL];
    __shared__ float s_part[16];
    __shared__ float s_mu, s_rstd;

    const int r = blockIdx.x;
    const int t = threadIdx.x;
    const float* xr = x + (size_t)r * DMODEL;
    const float* ar = ao + (size_t)r * DMODEL;

    float sum = 0.f, sq = 0.f;
    for (int d = t; d < DMODEL; d += 256) {
        float y = xr[d] + ar[d];
        ys[d] = y;
        sum += y;
        sq  += y * y;
    }
    #pragma unroll
    for (int off = 16; off > 0; off >>= 1) {
        sum += __shfl_xor_sync(0xffffffffu, sum, off);
        sq  += __shfl_xor_sync(0xffffffffu, sq, off);
    }
    const int wid = t >> 5, lane = t & 31;
    if (lane == 0) { s_part[wid] = sum; s_part[8 + wid] = sq; }
    __syncthreads();
    if (t == 0) {
        float S = 0.f, Q = 0.f;
        #pragma unroll
        for (int w = 0; w < 8; w++) { S += s_part[w]; Q += s_part[8 + w]; }
        float mu  = S * (1.f / DMODEL);
        float var = Q * (1.f / DMODEL) - mu * mu;
        s_mu = mu;
        s_rstd = rsqrtf(var + 1e-5f);
    }
    __syncthreads();
    const float mu = s_mu, rstd = s_rstd;
    float* outr = out + (size_t)r * DMODEL;
    for (int d = t; d < DMODEL; d += 256)
        outr[d] = gamma[d] * (ys[d] - mu) * rstd + beta[d];
}

// ---------------------------------------------------------------------------
extern "C" void kernel_launch(void* const* d_in, const int* in_sizes, int n_in,
                              void* d_out, int out_size)
{
    const float* x     = (const float*)d_in[0];
    const float* Wq    = (const float*)d_in[1];
    const float* bq    = (const float*)d_in[2];
    const float* Wk    = (const float*)d_in[3];
    const float* bk    = (const float*)d_in[4];
    const float* Wv    = (const float*)d_in[5];
    const float* bv    = (const float*)d_in[6];
    const float* Wo    = (const float*)d_in[7];
    const float* bo    = (const float*)d_in[8];
    const float* gamma = (const float*)d_in[9];
    const float* beta  = (const float*)d_in[10];

    float* out    = (float*)d_out;
    float* ln_out = out;
    float* ao_out = out + CHUNK_E;
    float* k_out  = out + 2 * CHUNK_E;   // [B,H,S,Dh]
    float* v_out  = out + 3 * CHUNK_E;   // [B,H,S,Dh]

    float *qptr = nullptr, *ctxptr = nullptr, *wtptr = nullptr, *xptr = nullptr;
    float *krptr = nullptr, *vtptr = nullptr;
    cudaGetSymbolAddress((void**)&qptr,   g_q);
    cudaGetSymbolAddress((void**)&ctxptr, g_ctx);
    cudaGetSymbolAddress((void**)&wtptr,  g_wt);
    cudaGetSymbolAddress((void**)&xptr,   g_x);
    cudaGetSymbolAddress((void**)&krptr,  g_kr);
    cudaGetSymbolAddress((void**)&vtptr,  g_vt);
    float* wt_q = wtptr;
    float* wt_k = wtptr + 1ULL * DMODEL * DMODEL;
    float* wt_v = wtptr + 2ULL * DMODEL * DMODEL;
    float* wt_o = wtptr + 3ULL * DMODEL * DMODEL;

    cudaFuncSetAttribute(gemm_tf32_kernel,
                         cudaFuncAttributeMaxDynamicSharedMemorySize, GEMM_SMEM);
    cudaFuncSetAttribute(attn_tc_kernel,
                         cudaFuncAttributeMaxDynamicSharedMemorySize, ATTN2_SMEM);

    // Pre-round x and W^T to tf32
    round_tf32_kernel<<<(int)(CHUNK_E / 4 / 256), 256>>>(x, xptr);
    dim3 tg(DMODEL / 32, DMODEL / 32), tb(32, 8);
    transpose_kernel<<<tg, tb>>>(Wq, wt_q);
    transpose_kernel<<<tg, tb>>>(Wk, wt_k);
    transpose_kernel<<<tg, tb>>>(Wv, wt_v);
    transpose_kernel<<<tg, tb>>>(Wo, wt_o);

    const float qscale = 0.08838834764831845f;  // 1/sqrt(128)
    dim3 gemm_grid(DMODEL / 128, NROWS / 128);

    gemm_tf32_kernel<<<gemm_grid, 256, GEMM_SMEM>>>(xptr, wt_q, bq, qptr,  nullptr, qscale, 1);
    gemm_tf32_kernel<<<gemm_grid, 256, GEMM_SMEM>>>(xptr, wt_k, bk, k_out, krptr,   1.0f,   1);
    gemm_tf32_kernel<<<gemm_grid, 256, GEMM_SMEM>>>(xptr, wt_v, bv, v_out, nullptr, 1.0f,   1);

    // per-head V transpose (attention B operand)
    dim3 vg(SEQ / 32, DH / 32, BATCH * NHEADS), vb2(32, 8);
    vtrans_kernel<<<vg, vb2>>>(v_out, vtptr);

    dim3 attn_grid(SEQ / BQ, NHEADS, BATCH);
    attn_tc_kernel<<<attn_grid, 256, ATTN2_SMEM>>>(krptr, vtptr);

    gemm_tf32_kernel<<<gemm_grid, 256, GEMM_SMEM>>>(ctxptr, wt_o, bo, ao_out, nullptr, 1.0f, 0);

    ln_kernel<<<NROWS, 256>>>(x, ao_out, gamma, beta, ln_out);
}

// round 6
// speedup vs baseline: 3.9730x; 1.0685x over previous
#include <cuda_runtime.h>
#include <cstdint>

// ---------------------------------------------------------------------------
// Problem constants
// ---------------------------------------------------------------------------
#define BATCH   2
#define SEQ     2048
#define DMODEL  2048
#define NHEADS  16
#define DH      128
#define NROWS   (BATCH*SEQ)              // 4096
#define CHUNK_E ((size_t)NROWS*DMODEL)

// Scratch (__device__ globals: allocation-free rule)
__device__ float g_q  [(size_t)BATCH*NHEADS*SEQ*DH];   // Q [B,H,S,Dh], pre-scaled
__device__ float g_ctx[(size_t)NROWS*DMODEL];          // ctx (tf32-rounded)
__device__ float g_wt [4ULL*DMODEL*DMODEL];            // W^T (tf32-rounded)
__device__ float g_x  [(size_t)NROWS*DMODEL];          // x (tf32-rounded)
__device__ float g_kr [(size_t)BATCH*NHEADS*SEQ*DH];   // K (tf32-rounded)
__device__ float g_vt [(size_t)BATCH*NHEADS*DH*SEQ];   // V^T [B,H,Dh,S] (tf32-rounded)

// ---------------------------------------------------------------------------
// PTX helpers (baseline features only: work under compute_103)
// ---------------------------------------------------------------------------
__device__ __forceinline__ uint32_t smem_u32(const void* p) {
    uint32_t a;
    asm("{ .reg .u64 t; cvta.to.shared.u64 t, %1; cvt.u32.u64 %0, t; }"
        : "=r"(a) : "l"(p));
    return a;
}
__device__ __forceinline__ float tf32r(float x) {
    float r;
    asm("cvt.rna.tf32.f32 %0, %1;" : "=f"(r) : "f"(x));
    return r;
}
#define CP_ASYNC16(dst, src) \
    asm volatile("cp.async.cg.shared.global [%0], [%1], 16;" :: "r"(dst), "l"(src))
#define CP_COMMIT()  asm volatile("cp.async.commit_group;" ::: "memory")
#define CP_WAIT1()   asm volatile("cp.async.wait_group 1;" ::: "memory")
#define CP_WAIT0()   asm volatile("cp.async.wait_group 0;" ::: "memory")

__device__ __forceinline__ void ldsm_x4(uint32_t& r0, uint32_t& r1,
                                        uint32_t& r2, uint32_t& r3, uint32_t a) {
    asm volatile("ldmatrix.sync.aligned.m8n8.x4.shared.b16 {%0,%1,%2,%3}, [%4];"
                 : "=r"(r0), "=r"(r1), "=r"(r2), "=r"(r3) : "r"(a));
}
__device__ __forceinline__ void mma_tf32(float* c, const uint32_t* a,
                                         uint32_t b0, uint32_t b1) {
    asm volatile(
        "mma.sync.aligned.m16n8k8.row.col.f32.tf32.tf32.f32 "
        "{%0,%1,%2,%3},{%4,%5,%6,%7},{%8,%9},{%0,%1,%2,%3};"
        : "+f"(c[0]), "+f"(c[1]), "+f"(c[2]), "+f"(c[3])
        : "r"(a[0]), "r"(a[1]), "r"(a[2]), "r"(a[3]), "r"(b0), "r"(b1));
}

// ---------------------------------------------------------------------------
// tf32-rounded copy
// ---------------------------------------------------------------------------
__global__ __launch_bounds__(256) void round_tf32_kernel(
    const float* __restrict__ in, float* __restrict__ out)
{
    const int i = blockIdx.x * 256 + threadIdx.x;
    float4 v = ((const float4*)in)[i];
    v.x = tf32r(v.x); v.y = tf32r(v.y); v.z = tf32r(v.z); v.w = tf32r(v.w);
    ((float4*)out)[i] = v;
}

// ---------------------------------------------------------------------------
// Fused 4-way weight transpose (+ tf32 rounding): out_z[n][k] = round(W_z[k][n])
// ---------------------------------------------------------------------------
__global__ __launch_bounds__(256) void transpose4_kernel(
    const float* __restrict__ W0, const float* __restrict__ W1,
    const float* __restrict__ W2, const float* __restrict__ W3,
    float* __restrict__ outBase)
{
    __shared__ float t[32][33];
    const int z = blockIdx.z;
    const float* in = (z == 0) ? W0 : (z == 1) ? W1 : (z == 2) ? W2 : W3;
    float* out = outBase + (size_t)z * DMODEL * DMODEL;

    const int x  = blockIdx.x * 32 + threadIdx.x;
    const int y0 = blockIdx.y * 32 + threadIdx.y;
    #pragma unroll
    for (int j = 0; j < 4; j++)
        t[threadIdx.y + j * 8][threadIdx.x] = in[(size_t)(y0 + j * 8) * DMODEL + x];
    __syncthreads();
    const int x2  = blockIdx.y * 32 + threadIdx.x;
    const int y20 = blockIdx.x * 32 + threadIdx.y;
    #pragma unroll
    for (int j = 0; j < 4; j++)
        out[(size_t)(y20 + j * 8) * DMODEL + x2] =
            tf32r(t[threadIdx.x][threadIdx.y + j * 8]);
}

// ---------------------------------------------------------------------------
// V transpose per head: vt[bh][d][s] = round(v[bh][s][d])
// ---------------------------------------------------------------------------
__global__ __launch_bounds__(256) void vtrans_kernel(
    const float* __restrict__ v, float* __restrict__ vt)
{
    __shared__ float t[32][33];
    const int bh = blockIdx.z;
    const float* in = v + (size_t)bh * SEQ * DH;
    float* out = vt + (size_t)bh * DH * SEQ;
    const int s0 = blockIdx.x * 32, d0 = blockIdx.y * 32;
    #pragma unroll
    for (int j = 0; j < 4; j++)
        t[threadIdx.y + j * 8][threadIdx.x] =
            in[(size_t)(s0 + threadIdx.y + j * 8) * DH + d0 + threadIdx.x];
    __syncthreads();
    #pragma unroll
    for (int j = 0; j < 4; j++)
        out[(size_t)(d0 + threadIdx.y + j * 8) * SEQ + s0 + threadIdx.x] =
            tf32r(t[threadIdx.x][threadIdx.y + j * 8]);
}

// ---------------------------------------------------------------------------
// Shared TF32 GEMM mainloop (3-stage cp.async, 128x128 tile, BK=32)
// ---------------------------------------------------------------------------
#define BK 32
#define NCHUNK (DMODEL / BK)          // 64
#define LDS_STRIDE 36
#define ROWB (LDS_STRIDE * 4)
#define TILE_B (128 * ROWB)           // 18432 bytes per stage buffer
#define GEMM_SMEM (6 * TILE_B)        // 110592: A stages [0,3), B stages [3,6)

__device__ __forceinline__ void gemm_mainloop(
    const float* __restrict__ Ab, const float* __restrict__ Bb,
    char* smc, uint32_t sb, int tid, float acc[4][4][4])
{
    const int wid = tid >> 5, lane = tid & 31;
    const int grow = tid >> 3;
    const int gcol = (tid & 7) * 4;
    const int wm = wid & 1, wn = wid >> 1;
    const int r7 = lane & 7, sel = lane >> 3;

    const uint32_t aoff = (uint32_t)((wm * 64 + (sel & 1) * 8 + r7) * ROWB
                                   + (sel >> 1) * 16);
    const uint32_t boff = (uint32_t)((wn * 32 + (sel >> 1) * 8 + r7) * ROWB
                                   + (sel & 1) * 16);

    auto load_chunk = [&](int chunk, int p) {
        const float* as = Ab + (size_t)grow * DMODEL + chunk * BK + gcol;
        const float* bs = Bb + (size_t)grow * DMODEL + chunk * BK + gcol;
        const uint32_t ad = sb + p * TILE_B       + grow * ROWB + gcol * 4;
        const uint32_t bd = sb + (3 + p) * TILE_B + grow * ROWB + gcol * 4;
        #pragma unroll
        for (int r = 0; r < 4; r++) {
            CP_ASYNC16(ad + r * 32 * ROWB, as + (size_t)r * 32 * DMODEL);
            CP_ASYNC16(bd + r * 32 * ROWB, bs + (size_t)r * 32 * DMODEL);
        }
    };

    #pragma unroll
    for (int mt = 0; mt < 4; mt++)
        #pragma unroll
        for (int nt = 0; nt < 4; nt++)
            #pragma unroll
            for (int q = 0; q < 4; q++) acc[mt][nt][q] = 0.f;

    load_chunk(0, 0); CP_COMMIT();
    load_chunk(1, 1); CP_COMMIT();

    int p = 0;
    for (int i = 0; i < NCHUNK; i++) {
        if (i < NCHUNK - 1) { CP_WAIT1(); } else { CP_WAIT0(); }
        __syncthreads();
        if (i + 2 < NCHUNK) {
            int pn = p + 2; if (pn >= 3) pn -= 3;
            load_chunk(i + 2, pn);
            CP_COMMIT();
        }

        const uint32_t sa  = sb + p * TILE_B + aoff;
        const uint32_t sbb = sb + (3 + p) * TILE_B + boff;
        #pragma unroll
        for (int ks = 0; ks < 4; ks++) {
            uint32_t a[4][4], b[2][4];
            #pragma unroll
            for (int mt = 0; mt < 4; mt++)
                ldsm_x4(a[mt][0], a[mt][1], a[mt][2], a[mt][3],
                        sa + mt * 16 * ROWB + ks * 32);
            #pragma unroll
            for (int np = 0; np < 2; np++)
                ldsm_x4(b[np][0], b[np][1], b[np][2], b[np][3],
                        sbb + np * 16 * ROWB + ks * 32);
            #pragma unroll
            for (int mt = 0; mt < 4; mt++)
                #pragma unroll
                for (int nt = 0; nt < 4; nt++)
                    mma_tf32(acc[mt][nt], a[mt],
                             b[nt >> 1][(nt & 1) * 2], b[nt >> 1][(nt & 1) * 2 + 1]);
        }
        if (++p == 3) p = 0;
    }
}

// ---------------------------------------------------------------------------
// Fused Q/K/V projection GEMM: blockIdx.z selects {Q,K,V}.
//   C_z = scale_z * (x @ Wt_z^T + bias_z) scattered to [B,H,S,Dh];
//   z==1 (K) also writes tf32-rounded copy Ck2.
// ---------------------------------------------------------------------------
__global__ __launch_bounds__(256, 2) void gemm_qkv_kernel(
    const float* __restrict__ A, const float* __restrict__ WtBase,
    const float* __restrict__ bq, const float* __restrict__ bk,
    const float* __restrict__ bv,
    float* __restrict__ Cq, float* __restrict__ Ck, float* __restrict__ Cv,
    float* __restrict__ Ck2, float qscale)
{
    extern __shared__ char smc[];
    const uint32_t sb = smem_u32(smc);
    const int tid = threadIdx.x;
    const int wid = tid >> 5, lane = tid & 31;
    const int bx = blockIdx.x, by = blockIdx.y, z = blockIdx.z;

    const float* Bt   = WtBase + (size_t)z * DMODEL * DMODEL;
    const float* bias = (z == 0) ? bq : (z == 1) ? bk : bv;
    float* C  = (z == 0) ? Cq : (z == 1) ? Ck : Cv;
    float* C2 = (z == 1) ? Ck2 : nullptr;
    const float scale = (z == 0) ? qscale : 1.0f;

    const float* Ab = A  + (size_t)(by * 128) * DMODEL;
    const float* Bb = Bt + (size_t)(bx * 128) * DMODEL;

    float acc[4][4][4];
    gemm_mainloop(Ab, Bb, smc, sb, tid, acc);

    const int wm = wid & 1, wn = wid >> 1;
    const int qr = lane >> 2, qc = (lane & 3) * 2;
    #pragma unroll
    for (int nt = 0; nt < 4; nt++) {
        const int dh = wn * 32 + nt * 8 + qc;
        const float bv0 = bias[bx * 128 + dh];
        const float bv1 = bias[bx * 128 + dh + 1];
        #pragma unroll
        for (int mt = 0; mt < 4; mt++) {
            #pragma unroll
            for (int half = 0; half < 2; half++) {
                const int mrow = by * 128 + wm * 64 + mt * 16 + half * 8 + qr;
                float2 r;
                r.x = (acc[mt][nt][half * 2 + 0] + bv0) * scale;
                r.y = (acc[mt][nt][half * 2 + 1] + bv1) * scale;
                const int b = mrow >> 11, s = mrow & 2047;
                const size_t idx = (((size_t)(b * NHEADS + bx) * SEQ + s) * DH) + dh;
                *(float2*)(C + idx) = r;
                if (C2) {
                    float2 r2 = make_float2(tf32r(r.x), tf32r(r.y));
                    *(float2*)(C2 + idx) = r2;
                }
            }
        }
    }
}

// ---------------------------------------------------------------------------
// Output projection GEMM: C = ctx @ Wo^T + bo, row-major out
// ---------------------------------------------------------------------------
__global__ __launch_bounds__(256, 2) void gemm_o_kernel(
    const float* __restrict__ A, const float* __restrict__ Bt,
    const float* __restrict__ bias, float* __restrict__ C)
{
    extern __shared__ char smc[];
    const uint32_t sb = smem_u32(smc);
    const int tid = threadIdx.x;
    const int wid = tid >> 5, lane = tid & 31;
    const int bx = blockIdx.x, by = blockIdx.y;

    const float* Ab = A  + (size_t)(by * 128) * DMODEL;
    const float* Bb = Bt + (size_t)(bx * 128) * DMODEL;

    float acc[4][4][4];
    gemm_mainloop(Ab, Bb, smc, sb, tid, acc);

    const int wm = wid & 1, wn = wid >> 1;
    const int qr = lane >> 2, qc = (lane & 3) * 2;
    #pragma unroll
    for (int nt = 0; nt < 4; nt++) {
        const int dh = wn * 32 + nt * 8 + qc;
        const float bv0 = bias[bx * 128 + dh];
        const float bv1 = bias[bx * 128 + dh + 1];
        #pragma unroll
        for (int mt = 0; mt < 4; mt++) {
            #pragma unroll
            for (int half = 0; half < 2; half++) {
                const int mrow = by * 128 + wm * 64 + mt * 16 + half * 8 + qr;
                float2 r;
                r.x = acc[mt][nt][half * 2 + 0] + bv0;
                r.y = acc[mt][nt][half * 2 + 1] + bv1;
                *(float2*)(C + (size_t)mrow * DMODEL + bx * 128 + dh) = r;
            }
        }
    }
}

// ---------------------------------------------------------------------------
// Tensor-core causal flash attention. Heavy-first CTA order (qb reversed).
// ---------------------------------------------------------------------------
#define BQ 128
#define BJ 64
#define KS_ST 132
#define VT_ST 68
#define PS_ST 72
#define SK_OFF(p) ((p) * (BJ * KS_ST * 4))
#define SV_OFF(p) (2 * (BJ * KS_ST * 4) + (p) * (DH * VT_ST * 4))
#define PS_OFF    (2 * (BJ * KS_ST * 4) + 2 * (DH * VT_ST * 4))
#define ATTN2_SMEM (PS_OFF + BQ * PS_ST * 4)

__global__ __launch_bounds__(256, 1) void attn_tc_kernel(
    const float* __restrict__ Kr, const float* __restrict__ Vt)
{
    extern __shared__ char smc[];
    const uint32_t sb = smem_u32(smc);
    const int tid = threadIdx.x, wid = tid >> 5, lane = tid & 31;
    const int qb = gridDim.x - 1 - blockIdx.x;      // heavy CTAs first
    const int h = blockIdx.y, b = blockIdx.z;
    const int q0 = qb * BQ;
    const int wq = wid * 16;
    const int r7 = lane & 7, sel = lane >> 3;
    const int qr = lane >> 2, qc2 = (lane & 3) * 2;

    const size_t headoff = (size_t)(b * NHEADS + h) * SEQ * DH;
    const float* qbase  = g_q + headoff;
    const float* kbase  = Kr  + headoff;
    const float* vtbase = Vt  + (size_t)(b * NHEADS + h) * DH * SEQ;

    #pragma unroll
    for (int i = 0; i < 16; i++) {
        const int idx = i * 256 + tid;
        const int row = idx >> 5, c4 = idx & 31;
        float4 v = *(const float4*)(qbase + (size_t)(q0 + row) * DH + c4 * 4);
        v.x = tf32r(v.x); v.y = tf32r(v.y); v.z = tf32r(v.z); v.w = tf32r(v.w);
        *(float4*)(smc + row * (KS_ST * 4) + c4 * 16) = v;
    }
    __syncthreads();
    uint32_t qf[16][4];
    {
        const uint32_t ab = sb + (wq + (sel & 1) * 8 + r7) * (KS_ST * 4)
                          + (sel >> 1) * 16;
        #pragma unroll
        for (int kt = 0; kt < 16; kt++)
            ldsm_x4(qf[kt][0], qf[kt][1], qf[kt][2], qf[kt][3], ab + kt * 32);
    }
    __syncthreads();

    auto prefetch = [&](int t, int p) {
        const int j0 = t * BJ;
        {
            const float* src = kbase + (size_t)(j0 + (tid >> 2)) * DH + (tid & 3) * 32;
            const uint32_t dst = sb + SK_OFF(p) + (tid >> 2) * (KS_ST * 4) + (tid & 3) * 128;
            #pragma unroll
            for (int i = 0; i < 8; i++) CP_ASYNC16(dst + i * 16, src + i * 4);
        }
        {
            const float* src = vtbase + (size_t)(tid >> 1) * SEQ + j0 + (tid & 1) * 32;
            const uint32_t dst = sb + SV_OFF(p) + (tid >> 1) * (VT_ST * 4) + (tid & 1) * 128;
            #pragma unroll
            for (int i = 0; i < 8; i++) CP_ASYNC16(dst + i * 16, src + i * 4);
        }
    };

    float oacc[16][4];
    #pragma unroll
    for (int nt = 0; nt < 16; nt++)
        #pragma unroll
        for (int q = 0; q < 4; q++) oacc[nt][q] = 0.f;
    float m[2] = {-1e30f, -1e30f}, l[2] = {0.f, 0.f};

    const int ntiles = 2 * qb + 2;
    prefetch(0, 0); CP_COMMIT();

    for (int t = 0; t < ntiles; t++) {
        const int p = t & 1;
        __syncthreads();
        if (t + 1 < ntiles) { prefetch(t + 1, 1 - p); CP_COMMIT(); CP_WAIT1(); }
        else                { CP_WAIT0(); }
        __syncthreads();

        const int j0 = t * BJ;
        if (j0 > q0 + wq + 15) continue;

        float sacc[8][4];
        #pragma unroll
        for (int nt = 0; nt < 8; nt++)
            #pragma unroll
            for (int q = 0; q < 4; q++) sacc[nt][q] = 0.f;

        const uint32_t kb0 = sb + SK_OFF(p)
                           + ((sel >> 1) * 8 + r7) * (KS_ST * 4) + (sel & 1) * 16;
        #pragma unroll
        for (int kt = 0; kt < 16; kt++) {
            #pragma unroll
            for (int np = 0; np < 4; np++) {
                uint32_t b0, b1, b2, b3;
                ldsm_x4(b0, b1, b2, b3, kb0 + np * 16 * (KS_ST * 4) + kt * 32);
                mma_tf32(sacc[2 * np],     qf[kt], b0, b1);
                mma_tf32(sacc[2 * np + 1], qf[kt], b2, b3);
            }
        }

        const int row0 = q0 + wq + qr;
        if (j0 + BJ - 1 > q0 + wq) {
            #pragma unroll
            for (int nt = 0; nt < 8; nt++) {
                const int c0 = j0 + nt * 8 + qc2;
                if (c0     > row0)     sacc[nt][0] = -1e30f;
                if (c0 + 1 > row0)     sacc[nt][1] = -1e30f;
                if (c0     > row0 + 8) sacc[nt][2] = -1e30f;
                if (c0 + 1 > row0 + 8) sacc[nt][3] = -1e30f;
            }
        }

        #pragma unroll
        for (int r = 0; r < 2; r++) {
            float rmax = -1e30f;
            #pragma unroll
            for (int nt = 0; nt < 8; nt++)
                rmax = fmaxf(rmax, fmaxf(sacc[nt][2 * r], sacc[nt][2 * r + 1]));
            rmax = fmaxf(rmax, __shfl_xor_sync(0xffffffffu, rmax, 1));
            rmax = fmaxf(rmax, __shfl_xor_sync(0xffffffffu, rmax, 2));
            const float mnew  = fmaxf(m[r], rmax);
            const float alpha = __expf(m[r] - mnew);
            float rsum = 0.f;
            #pragma unroll
            for (int nt = 0; nt < 8; nt++) {
                float p0 = __expf(sacc[nt][2 * r]     - mnew);
                float p1 = __expf(sacc[nt][2 * r + 1] - mnew);
                sacc[nt][2 * r] = p0; sacc[nt][2 * r + 1] = p1;
                rsum += p0 + p1;
            }
            rsum += __shfl_xor_sync(0xffffffffu, rsum, 1);
            rsum += __shfl_xor_sync(0xffffffffu, rsum, 2);
            l[r] = l[r] * alpha + rsum;
            m[r] = mnew;
            #pragma unroll
            for (int nt = 0; nt < 16; nt++) {
                oacc[nt][2 * r]     *= alpha;
                oacc[nt][2 * r + 1] *= alpha;
            }
        }

        {
            const uint32_t pbo = PS_OFF + (wq + qr) * (PS_ST * 4) + qc2 * 4;
            #pragma unroll
            for (int nt = 0; nt < 8; nt++) {
                float2 v0 = make_float2(tf32r(sacc[nt][0]), tf32r(sacc[nt][1]));
                float2 v1 = make_float2(tf32r(sacc[nt][2]), tf32r(sacc[nt][3]));
                *(float2*)(smc + pbo + nt * 32)                    = v0;
                *(float2*)(smc + pbo + 8 * (PS_ST * 4) + nt * 32)  = v1;
            }
        }
        __syncwarp();

        const uint32_t pab = sb + PS_OFF
                           + (wq + (sel & 1) * 8 + r7) * (PS_ST * 4) + (sel >> 1) * 16;
        const uint32_t vb0 = sb + SV_OFF(p)
                           + ((sel >> 1) * 8 + r7) * (VT_ST * 4) + (sel & 1) * 16;
        #pragma unroll
        for (int kt = 0; kt < 8; kt++) {
            uint32_t pa[4];
            ldsm_x4(pa[0], pa[1], pa[2], pa[3], pab + kt * 32);
            #pragma unroll
            for (int np = 0; np < 8; np++) {
                uint32_t b0, b1, b2, b3;
                ldsm_x4(b0, b1, b2, b3, vb0 + np * 16 * (VT_ST * 4) + kt * 32);
                mma_tf32(oacc[2 * np],     pa, b0, b1);
                mma_tf32(oacc[2 * np + 1], pa, b2, b3);
            }
        }
    }

    const float inv0 = 1.f / l[0], inv1 = 1.f / l[1];
    float* crow0 = g_ctx + (size_t)(b * SEQ + q0 + wq + qr) * DMODEL + h * DH + qc2;
    float* crow1 = crow0 + 8 * DMODEL;
    #pragma unroll
    for (int nt = 0; nt < 16; nt++) {
        float2 v0 = make_float2(tf32r(oacc[nt][0] * inv0), tf32r(oacc[nt][1] * inv0));
        float2 v1 = make_float2(tf32r(oacc[nt][2] * inv1), tf32r(oacc[nt][3] * inv1));
        *(float2*)(crow0 + nt * 8) = v0;
        *(float2*)(crow1 + nt * 8) = v1;
    }
}

// ---------------------------------------------------------------------------
// Residual + LayerNorm
// ---------------------------------------------------------------------------
__global__ __launch_bounds__(256) void ln_kernel(
    const float* __restrict__ x, const float* __restrict__ ao,
    const float* __restrict__ gamma, const float* __restrict__ beta,
    float* __restrict__ out)
{
    __shared__ float ys[DMODEL];
    __shared__ float s_part[16];
    __shared__ float s_mu, s_rstd;

    const int r = blockIdx.x;
    const int t = threadIdx.x;
    const float* xr = x + (size_t)r * DMODEL;
    const float* ar = ao + (size_t)r * DMODEL;

    float sum = 0.f, sq = 0.f;
    for (int d = t; d < DMODEL; d += 256) {
        float y = xr[d] + ar[d];
        ys[d] = y;
        sum += y;
        sq  += y * y;
    }
    #pragma unroll
    for (int off = 16; off > 0; off >>= 1) {
        sum += __shfl_xor_sync(0xffffffffu, sum, off);
        sq  += __shfl_xor_sync(0xffffffffu, sq, off);
    }
    const int wid = t >> 5, lane = t & 31;
    if (lane == 0) { s_part[wid] = sum; s_part[8 + wid] = sq; }
    __syncthreads();
    if (t == 0) {
        float S = 0.f, Q = 0.f;
        #pragma unroll
        for (int w = 0; w < 8; w++) { S += s_part[w]; Q += s_part[8 + w]; }
        float mu  = S * (1.f / DMODEL);
        float var = Q * (1.f / DMODEL) - mu * mu;
        s_mu = mu;
        s_rstd = rsqrtf(var + 1e-5f);
    }
    __syncthreads();
    const float mu = s_mu, rstd = s_rstd;
    float* outr = out + (size_t)r * DMODEL;
    for (int d = t; d < DMODEL; d += 256)
        outr[d] = gamma[d] * (ys[d] - mu) * rstd + beta[d];
}

// ---------------------------------------------------------------------------
extern "C" void kernel_launch(void* const* d_in, const int* in_sizes, int n_in,
                              void* d_out, int out_size)
{
    const float* x     = (const float*)d_in[0];
    const float* Wq    = (const float*)d_in[1];
    const float* bq    = (const float*)d_in[2];
    const float* Wk    = (const float*)d_in[3];
    const float* bk    = (const float*)d_in[4];
    const float* Wv    = (const float*)d_in[5];
    const float* bv    = (const float*)d_in[6];
    const float* Wo    = (const float*)d_in[7];
    const float* bo    = (const float*)d_in[8];
    const float* gamma = (const float*)d_in[9];
    const float* beta  = (const float*)d_in[10];

    float* out    = (float*)d_out;
    float* ln_out = out;
    float* ao_out = out + CHUNK_E;
    float* k_out  = out + 2 * CHUNK_E;   // [B,H,S,Dh]
    float* v_out  = out + 3 * CHUNK_E;   // [B,H,S,Dh]

    float *qptr = nullptr, *ctxptr = nullptr, *wtptr = nullptr, *xptr = nullptr;
    float *krptr = nullptr, *vtptr = nullptr;
    cudaGetSymbolAddress((void**)&qptr,   g_q);
    cudaGetSymbolAddress((void**)&ctxptr, g_ctx);
    cudaGetSymbolAddress((void**)&wtptr,  g_wt);
    cudaGetSymbolAddress((void**)&xptr,   g_x);
    cudaGetSymbolAddress((void**)&krptr,  g_kr);
    cudaGetSymbolAddress((void**)&vtptr,  g_vt);
    float* wt_o = wtptr + 3ULL * DMODEL * DMODEL;

    cudaFuncSetAttribute(gemm_qkv_kernel,
                         cudaFuncAttributeMaxDynamicSharedMemorySize, GEMM_SMEM);
    cudaFuncSetAttribute(gemm_o_kernel,
                         cudaFuncAttributeMaxDynamicSharedMemorySize, GEMM_SMEM);
    cudaFuncSetAttribute(attn_tc_kernel,
                         cudaFuncAttributeMaxDynamicSharedMemorySize, ATTN2_SMEM);

    // Pre-round x; fused 4-way W^T transpose (order in g_wt: q,k,v,o)
    round_tf32_kernel<<<(int)(CHUNK_E / 4 / 256), 256>>>(x, xptr);
    dim3 tg(DMODEL / 32, DMODEL / 32, 4), tb(32, 8);
    transpose4_kernel<<<tg, tb>>>(Wq, Wk, Wv, Wo, wtptr);

    const float qscale = 0.08838834764831845f;  // 1/sqrt(128)

    // Fused Q/K/V projections: one launch, 1536 CTAs (kills wave tail)
    dim3 qkv_grid(DMODEL / 128, NROWS / 128, 3);
    gemm_qkv_kernel<<<qkv_grid, 256, GEMM_SMEM>>>(
        xptr, wtptr, bq, bk, bv, qptr, k_out, v_out, krptr, qscale);

    // per-head V transpose (attention B operand)
    dim3 vg(SEQ / 32, DH / 32, BATCH * NHEADS), vb2(32, 8);
    vtrans_kernel<<<vg, vb2>>>(v_out, vtptr);

    dim3 attn_grid(SEQ / BQ, NHEADS, BATCH);
    attn_tc_kernel<<<attn_grid, 256, ATTN2_SMEM>>>(krptr, vtptr);

    dim3 o_grid(DMODEL / 128, NROWS / 128);
    gemm_o_kernel<<<o_grid, 256, GEMM_SMEM>>>(ctxptr, wt_o, bo, ao_out);

    ln_kernel<<<NROWS, 256>>>(x, ao_out, gamma, beta, ln_out);
}

// round 9
// speedup vs baseline: 5.8931x; 1.4833x over previous
#include <cuda_runtime.h>
#include <cuda_fp16.h>
#include <cstdint>

// ---------------------------------------------------------------------------
// Problem constants
// ---------------------------------------------------------------------------
#define BATCH   2
#define SEQ     2048
#define DMODEL  2048
#define NHEADS  16
#define DH      128
#define NROWS   (BATCH*SEQ)              // 4096
#define CHUNK_E ((size_t)NROWS*DMODEL)

// Scratch (__device__ globals: allocation-free rule). All mma operands fp16.
__device__ __half g_q  [(size_t)BATCH*NHEADS*SEQ*DH];   // Q [B,H,S,Dh], pre-scaled
__device__ __half g_ctx[(size_t)NROWS*DMODEL];          // attention ctx
__device__ __half g_wt [4ULL*DMODEL*DMODEL];            // W^T for q,k,v,o
__device__ __half g_x  [(size_t)NROWS*DMODEL];          // x
__device__ __half g_kr [(size_t)BATCH*NHEADS*SEQ*DH];   // K
__device__ __half g_vt [(size_t)BATCH*NHEADS*DH*SEQ];   // V^T [B,H,Dh,S]

// ---------------------------------------------------------------------------
// PTX helpers (baseline features only: work under compute_103)
// ---------------------------------------------------------------------------
__device__ __forceinline__ uint32_t smem_u32(const void* p) {
    uint32_t a;
    asm("{ .reg .u64 t; cvta.to.shared.u64 t, %1; cvt.u32.u64 %0, t; }"
        : "=r"(a) : "l"(p));
    return a;
}
#define CP_ASYNC16(dst, src) \
    asm volatile("cp.async.cg.shared.global [%0], [%1], 16;" :: "r"(dst), "l"(src))
#define CP_COMMIT()  asm volatile("cp.async.commit_group;" ::: "memory")
#define CP_WAIT1()   asm volatile("cp.async.wait_group 1;" ::: "memory")
#define CP_WAIT0()   asm volatile("cp.async.wait_group 0;" ::: "memory")

__device__ __forceinline__ void ldsm_x4(uint32_t& r0, uint32_t& r1,
                                        uint32_t& r2, uint32_t& r3, uint32_t a) {
    asm volatile("ldmatrix.sync.aligned.m8n8.x4.shared.b16 {%0,%1,%2,%3}, [%4];"
                 : "=r"(r0), "=r"(r1), "=r"(r2), "=r"(r3) : "r"(a));
}
// fp16 mma, fp32 accumulate: m16n8k16
__device__ __forceinline__ void mma_f16(float* c, const uint32_t* a,
                                        uint32_t b0, uint32_t b1) {
    asm volatile(
        "mma.sync.aligned.m16n8k16.row.col.f32.f16.f16.f32 "
        "{%0,%1,%2,%3},{%4,%5,%6,%7},{%8,%9},{%0,%1,%2,%3};"
        : "+f"(c[0]), "+f"(c[1]), "+f"(c[2]), "+f"(c[3])
        : "r"(a[0]), "r"(a[1]), "r"(a[2]), "r"(a[3]), "r"(b0), "r"(b1));
}

// ---------------------------------------------------------------------------
// fp32 -> fp16 copy (8 elems/thread)
// ---------------------------------------------------------------------------
__global__ __launch_bounds__(256) void tohalf_kernel(
    const float* __restrict__ in, __half* __restrict__ out)
{
    const int i = blockIdx.x * 256 + threadIdx.x;
    float4 v0 = ((const float4*)in)[2 * i];
    float4 v1 = ((const float4*)in)[2 * i + 1];
    half2 h[4];
    h[0] = __floats2half2_rn(v0.x, v0.y);
    h[1] = __floats2half2_rn(v0.z, v0.w);
    h[2] = __floats2half2_rn(v1.x, v1.y);
    h[3] = __floats2half2_rn(v1.z, v1.w);
    ((float4*)out)[i] = *(float4*)h;
}

// ---------------------------------------------------------------------------
// Fused 4-way weight transpose to fp16: out_z[n][k] = half(W_z[k][n])
// ---------------------------------------------------------------------------
__global__ __launch_bounds__(256) void transpose4_kernel(
    const float* __restrict__ W0, const float* __restrict__ W1,
    const float* __restrict__ W2, const float* __restrict__ W3,
    __half* __restrict__ outBase)
{
    __shared__ float t[32][33];
    const int z = blockIdx.z;
    const float* in = (z == 0) ? W0 : (z == 1) ? W1 : (z == 2) ? W2 : W3;
    __half* out = outBase + (size_t)z * DMODEL * DMODEL;

    const int x  = blockIdx.x * 32 + threadIdx.x;
    const int y0 = blockIdx.y * 32 + threadIdx.y;
    #pragma unroll
    for (int j = 0; j < 4; j++)
        t[threadIdx.y + j * 8][threadIdx.x] = in[(size_t)(y0 + j * 8) * DMODEL + x];
    __syncthreads();
    const int x2  = blockIdx.y * 32 + threadIdx.x;
    const int y20 = blockIdx.x * 32 + threadIdx.y;
    #pragma unroll
    for (int j = 0; j < 4; j++)
        out[(size_t)(y20 + j * 8) * DMODEL + x2] =
            __float2half_rn(t[threadIdx.x][threadIdx.y + j * 8]);
}

// ---------------------------------------------------------------------------
// V transpose per head to fp16: vt[bh][d][s] = half(v[bh][s][d])
// ---------------------------------------------------------------------------
__global__ __launch_bounds__(256) void vtrans_kernel(
    const float* __restrict__ v, __half* __restrict__ vt)
{
    __shared__ float t[32][33];
    const int bh = blockIdx.z;
    const float* in = v + (size_t)bh * SEQ * DH;
    __half* out = vt + (size_t)bh * DH * SEQ;
    const int s0 = blockIdx.x * 32, d0 = blockIdx.y * 32;
    #pragma unroll
    for (int j = 0; j < 4; j++)
        t[threadIdx.y + j * 8][threadIdx.x] =
            in[(size_t)(s0 + threadIdx.y + j * 8) * DH + d0 + threadIdx.x];
    __syncthreads();
    #pragma unroll
    for (int j = 0; j < 4; j++)
        out[(size_t)(d0 + threadIdx.y + j * 8) * SEQ + s0 + threadIdx.x] =
            __float2half_rn(t[threadIdx.x][threadIdx.y + j * 8]);
}

// ---------------------------------------------------------------------------
// fp16 mma GEMM mainloop: 128x128 CTA tile, BK=64, 3-stage cp.async ring.
//   Stage safety: compute stage p; chunk i+1 in (p+1)%3; prefetch i+2 into
//   (p+2)%3; top-of-loop __syncthreads orders reuse of stage p at i+1.
// ---------------------------------------------------------------------------
#define BK 64
#define NCHUNK (DMODEL / BK)          // 32
#define ROWB 144
#define TILE_B (128 * ROWB)           // 18432 bytes per matrix per stage
#define STAGE_B (2 * TILE_B)          // A+B per stage: 36864
#define GEMM_SMEM (3 * STAGE_B)       // 110592

__device__ __forceinline__ void gemm_mainloop(
    const __half* __restrict__ Ab, const __half* __restrict__ Bb,
    uint32_t sb, int tid, float acc[4][4][4])
{
    const int wid = tid >> 5, lane = tid & 31;
    const int wm = wid & 1, wn = wid >> 1;
    const int r7 = lane & 7, sel = lane >> 3;

    const int grow = tid >> 1;            // 0..127
    const int gcolh = (tid & 1) * 32;     // halves (64B)

    const uint32_t aoff = (uint32_t)((wm * 64 + (sel & 1) * 8 + r7) * ROWB
                                   + (sel >> 1) * 16);
    const uint32_t boff = (uint32_t)((wn * 32 + (sel >> 1) * 8 + r7) * ROWB
                                   + (sel & 1) * 16);

    auto load_chunk = [&](int chunk, int p) {
        const __half* as = Ab + (size_t)grow * DMODEL + chunk * BK + gcolh;
        const __half* bs = Bb + (size_t)grow * DMODEL + chunk * BK + gcolh;
        const uint32_t ad = sb + p * STAGE_B          + grow * ROWB + gcolh * 2;
        const uint32_t bd = sb + p * STAGE_B + TILE_B + grow * ROWB + gcolh * 2;
        #pragma unroll
        for (int i = 0; i < 4; i++) {
            CP_ASYNC16(ad + i * 16, as + i * 8);
            CP_ASYNC16(bd + i * 16, bs + i * 8);
        }
    };

    #pragma unroll
    for (int mt = 0; mt < 4; mt++)
        #pragma unroll
        for (int nt = 0; nt < 4; nt++)
            #pragma unroll
            for (int q = 0; q < 4; q++) acc[mt][nt][q] = 0.f;

    load_chunk(0, 0); CP_COMMIT();
    load_chunk(1, 1); CP_COMMIT();

    int p = 0;   // stage of chunk i
    for (int i = 0; i < NCHUNK; i++) {
        if (i < NCHUNK - 1) { CP_WAIT1(); } else { CP_WAIT0(); }
        __syncthreads();
        if (i + 2 < NCHUNK) {
            int pn = p + 2; if (pn >= 3) pn -= 3;
            load_chunk(i + 2, pn);
            CP_COMMIT();
        }

        const uint32_t sa  = sb + p * STAGE_B + aoff;
        const uint32_t sbb = sb + p * STAGE_B + TILE_B + boff;
        #pragma unroll
        for (int ks = 0; ks < 4; ks++) {          // k16 steps
            uint32_t a[4][4], b[2][4];
            #pragma unroll
            for (int mt = 0; mt < 4; mt++)
                ldsm_x4(a[mt][0], a[mt][1], a[mt][2], a[mt][3],
                        sa + mt * 16 * ROWB + ks * 32);
            #pragma unroll
            for (int np = 0; np < 2; np++)
                ldsm_x4(b[np][0], b[np][1], b[np][2], b[np][3],
                        sbb + np * 16 * ROWB + ks * 32);
            #pragma unroll
            for (int mt = 0; mt < 4; mt++)
                #pragma unroll
                for (int nt = 0; nt < 4; nt++)
                    mma_f16(acc[mt][nt], a[mt],
                            b[nt >> 1][(nt & 1) * 2], b[nt >> 1][(nt & 1) * 2 + 1]);
        }
        if (++p == 3) p = 0;
    }
}

// ---------------------------------------------------------------------------
// Fused Q/K/V projection GEMM. z: 0=Q (half out, scaled), 1=K (fp32 + half),
// 2=V (fp32 out).
// ---------------------------------------------------------------------------
__global__ __launch_bounds__(256, 2) void gemm_qkv_kernel(
    const __half* __restrict__ A, const __half* __restrict__ WtBase,
    const float* __restrict__ bq, const float* __restrict__ bk,
    const float* __restrict__ bv,
    __half* __restrict__ Cq, float* __restrict__ Ck, float* __restrict__ Cv,
    __half* __restrict__ Ck2, float qscale)
{
    extern __shared__ char smc[];
    const uint32_t sb = smem_u32(smc);
    const int tid = threadIdx.x;
    const int wid = tid >> 5, lane = tid & 31;
    const int bx = blockIdx.x, by = blockIdx.y, z = blockIdx.z;

    const __half* Bt  = WtBase + (size_t)z * DMODEL * DMODEL;
    const float* bias = (z == 0) ? bq : (z == 1) ? bk : bv;

    const __half* Ab = A  + (size_t)(by * 128) * DMODEL;
    const __half* Bb = Bt + (size_t)(bx * 128) * DMODEL;

    float acc[4][4][4];
    gemm_mainloop(Ab, Bb, sb, tid, acc);

    const int wm = wid & 1, wn = wid >> 1;
    const int qr = lane >> 2, qc = (lane & 3) * 2;
    #pragma unroll
    for (int nt = 0; nt < 4; nt++) {
        const int dh = wn * 32 + nt * 8 + qc;
        const float bv0 = bias[bx * 128 + dh];
        const float bv1 = bias[bx * 128 + dh + 1];
        #pragma unroll
        for (int mt = 0; mt < 4; mt++) {
            #pragma unroll
            for (int half_ = 0; half_ < 2; half_++) {
                const int mrow = by * 128 + wm * 64 + mt * 16 + half_ * 8 + qr;
                const int b = mrow >> 11, s = mrow & 2047;
                const size_t idx = (((size_t)(b * NHEADS + bx) * SEQ + s) * DH) + dh;
                float r0 = acc[mt][nt][half_ * 2 + 0] + bv0;
                float r1 = acc[mt][nt][half_ * 2 + 1] + bv1;
                if (z == 0) {
                    *(half2*)(Cq + idx) = __floats2half2_rn(r0 * qscale, r1 * qscale);
                } else if (z == 1) {
                    *(float2*)(Ck + idx) = make_float2(r0, r1);
                    *(half2*)(Ck2 + idx) = __floats2half2_rn(r0, r1);
                } else {
                    *(float2*)(Cv + idx) = make_float2(r0, r1);
                }
            }
        }
    }
}

// ---------------------------------------------------------------------------
// Output projection GEMM: C = ctx(half) @ Wo^T(half) + bo, fp32 row-major out
// ---------------------------------------------------------------------------
__global__ __launch_bounds__(256, 2) void gemm_o_kernel(
    const __half* __restrict__ A, const __half* __restrict__ Bt,
    const float* __restrict__ bias, float* __restrict__ C)
{
    extern __shared__ char smc[];
    const uint32_t sb = smem_u32(smc);
    const int tid = threadIdx.x;
    const int wid = tid >> 5, lane = tid & 31;
    const int bx = blockIdx.x, by = blockIdx.y;

    const __half* Ab = A  + (size_t)(by * 128) * DMODEL;
    const __half* Bb = Bt + (size_t)(bx * 128) * DMODEL;

    float acc[4][4][4];
    gemm_mainloop(Ab, Bb, sb, tid, acc);

    const int wm = wid & 1, wn = wid >> 1;
    const int qr = lane >> 2, qc = (lane & 3) * 2;
    #pragma unroll
    for (int nt = 0; nt < 4; nt++) {
        const int dh = wn * 32 + nt * 8 + qc;
        const float bv0 = bias[bx * 128 + dh];
        const float bv1 = bias[bx * 128 + dh + 1];
        #pragma unroll
        for (int mt = 0; mt < 4; mt++) {
            #pragma unroll
            for (int half_ = 0; half_ < 2; half_++) {
                const int mrow = by * 128 + wm * 64 + mt * 16 + half_ * 8 + qr;
                float2 r;
                r.x = acc[mt][nt][half_ * 2 + 0] + bv0;
                r.y = acc[mt][nt][half_ * 2 + 1] + bv1;
                *(float2*)(C + (size_t)mrow * DMODEL + bx * 128 + dh) = r;
            }
        }
    }
}

// ---------------------------------------------------------------------------
// fp16 tensor-core causal flash attention. Heavy-first CTA order.
//   256 thr, 128 q-rows/CTA (16/warp), BJ=64 key tile, fp32 softmax/acc.
//   K/V double buffer: prefetch(t+1, 1-p) never collides with compute(p).
// ---------------------------------------------------------------------------
#define BQ 128
#define BJ 64
#define QROWB 272
#define VROWB 144
#define PROWB 144
#define QS_B     (128 * QROWB)                     // 34816
#define SK_OFF(p) (QS_B + (p) * (BJ * QROWB))
#define SV_OFF(p) (QS_B + 2 * (BJ * QROWB) + (p) * (DH * VROWB))
#define PS_OFF    (QS_B + 2 * (BJ * QROWB) + 2 * (DH * VROWB))
#define ATTN2_SMEM (PS_OFF + BQ * PROWB)           // 124928

__global__ __launch_bounds__(256, 1) void attn_tc_kernel(
    const __half* __restrict__ Kr, const __half* __restrict__ Vt)
{
    extern __shared__ char smc[];
    const uint32_t sb = smem_u32(smc);
    const int tid = threadIdx.x, wid = tid >> 5, lane = tid & 31;
    const int qb = gridDim.x - 1 - blockIdx.x;      // heavy CTAs first
    const int h = blockIdx.y, b = blockIdx.z;
    const int q0 = qb * BQ;
    const int wq = wid * 16;
    const int r7 = lane & 7, sel = lane >> 3;
    const int qr = lane >> 2, qc2 = (lane & 3) * 2;

    const size_t headoff = (size_t)(b * NHEADS + h) * SEQ * DH;
    const __half* qbase  = g_q + headoff;
    const __half* kbase  = Kr  + headoff;
    const __half* vtbase = Vt  + (size_t)(b * NHEADS + h) * DH * SEQ;

    auto prefetch = [&](int t, int p) {
        const int j0 = t * BJ;
        {   // K tile: 64 rows x 128 halves (256B)
            const __half* src = kbase + (size_t)(j0 + (tid >> 2)) * DH + (tid & 3) * 32;
            const uint32_t dst = sb + SK_OFF(p) + (tid >> 2) * QROWB + (tid & 3) * 64;
            #pragma unroll
            for (int i = 0; i < 4; i++) CP_ASYNC16(dst + i * 16, src + i * 8);
        }
        {   // V^T tile: 128 rows x 64 halves (128B)
            const __half* src = vtbase + (size_t)(tid >> 1) * SEQ + j0 + (tid & 1) * 32;
            const uint32_t dst = sb + SV_OFF(p) + (tid >> 1) * VROWB + (tid & 1) * 64;
            #pragma unroll
            for (int i = 0; i < 4; i++) CP_ASYNC16(dst + i * 16, src + i * 8);
        }
    };

    // overlap tile-0 prefetch with Q staging
    prefetch(0, 0); CP_COMMIT();

    // stage Q (already fp16) into smem
    #pragma unroll
    for (int i = 0; i < 8; i++) {
        const int idx = i * 256 + tid;              // 2048 float4-chunks
        const int row = idx >> 4, c = idx & 15;     // 16 x 16B per 256B row
        *(float4*)(smc + row * QROWB + c * 16) =
            *(const float4*)(qbase + (size_t)(q0 + row) * DH + c * 8);
    }
    __syncthreads();
    uint32_t qf[8][4];
    {
        const uint32_t ab = sb + (wq + (sel & 1) * 8 + r7) * QROWB + (sel >> 1) * 16;
        #pragma unroll
        for (int ks = 0; ks < 8; ks++)
            ldsm_x4(qf[ks][0], qf[ks][1], qf[ks][2], qf[ks][3], ab + ks * 32);
    }

    float oacc[16][4];
    #pragma unroll
    for (int nt = 0; nt < 16; nt++)
        #pragma unroll
        for (int q = 0; q < 4; q++) oacc[nt][q] = 0.f;
    float m[2] = {-1e30f, -1e30f}, l[2] = {0.f, 0.f};

    const int ntiles = 2 * qb + 2;
    for (int t = 0; t < ntiles; t++) {
        const int p = t & 1;
        __syncthreads();
        if (t + 1 < ntiles) { prefetch(t + 1, 1 - p); CP_COMMIT(); CP_WAIT1(); }
        else                { CP_WAIT0(); }
        __syncthreads();

        const int j0 = t * BJ;
        if (j0 > q0 + wq + 15) continue;

        // ---- S = Q K^T (8 k16-steps over Dh) ----
        float sacc[8][4];
        #pragma unroll
        for (int nt = 0; nt < 8; nt++)
            #pragma unroll
            for (int q = 0; q < 4; q++) sacc[nt][q] = 0.f;

        const uint32_t kb0 = sb + SK_OFF(p)
                           + ((sel >> 1) * 8 + r7) * QROWB + (sel & 1) * 16;
        #pragma unroll
        for (int ks = 0; ks < 8; ks++) {
            #pragma unroll
            for (int np = 0; np < 4; np++) {
                uint32_t b0, b1, b2, b3;
                ldsm_x4(b0, b1, b2, b3, kb0 + np * 16 * QROWB + ks * 32);
                mma_f16(sacc[2 * np],     qf[ks], b0, b1);
                mma_f16(sacc[2 * np + 1], qf[ks], b2, b3);
            }
        }

        // ---- causal mask ----
        const int row0 = q0 + wq + qr;
        if (j0 + BJ - 1 > q0 + wq) {
            #pragma unroll
            for (int nt = 0; nt < 8; nt++) {
                const int c0 = j0 + nt * 8 + qc2;
                if (c0     > row0)     sacc[nt][0] = -1e30f;
                if (c0 + 1 > row0)     sacc[nt][1] = -1e30f;
                if (c0     > row0 + 8) sacc[nt][2] = -1e30f;
                if (c0 + 1 > row0 + 8) sacc[nt][3] = -1e30f;
            }
        }

        // ---- online softmax (2 rows per thread, fp32) ----
        #pragma unroll
        for (int r = 0; r < 2; r++) {
            float rmax = -1e30f;
            #pragma unroll
            for (int nt = 0; nt < 8; nt++)
                rmax = fmaxf(rmax, fmaxf(sacc[nt][2 * r], sacc[nt][2 * r + 1]));
            rmax = fmaxf(rmax, __shfl_xor_sync(0xffffffffu, rmax, 1));
            rmax = fmaxf(rmax, __shfl_xor_sync(0xffffffffu, rmax, 2));
            const float mnew  = fmaxf(m[r], rmax);
            const float alpha = __expf(m[r] - mnew);
            float rsum = 0.f;
            #pragma unroll
            for (int nt = 0; nt < 8; nt++) {
                float p0 = __expf(sacc[nt][2 * r]     - mnew);
                float p1 = __expf(sacc[nt][2 * r + 1] - mnew);
                sacc[nt][2 * r] = p0; sacc[nt][2 * r + 1] = p1;
                rsum += p0 + p1;
            }
            rsum += __shfl_xor_sync(0xffffffffu, rsum, 1);
            rsum += __shfl_xor_sync(0xffffffffu, rsum, 2);
            l[r] = l[r] * alpha + rsum;
            m[r] = mnew;
            #pragma unroll
            for (int nt = 0; nt < 16; nt++) {
                oacc[nt][2 * r]     *= alpha;
                oacc[nt][2 * r + 1] *= alpha;
            }
        }

        // ---- stage P (fp16) to warp-private smem ----
        {
            const uint32_t pbo = PS_OFF + (wq + qr) * PROWB + qc2 * 2;
            #pragma unroll
            for (int nt = 0; nt < 8; nt++) {
                *(half2*)(smc + pbo + nt * 16) =
                    __floats2half2_rn(sacc[nt][0], sacc[nt][1]);
                *(half2*)(smc + pbo + 8 * PROWB + nt * 16) =
                    __floats2half2_rn(sacc[nt][2], sacc[nt][3]);
            }
        }
        __syncwarp();

        // ---- O += P V (4 k16-steps over BJ) ----
        const uint32_t pab = sb + PS_OFF
                           + (wq + (sel & 1) * 8 + r7) * PROWB + (sel >> 1) * 16;
        const uint32_t vb0 = sb + SV_OFF(p)
                           + ((sel >> 1) * 8 + r7) * VROWB + (sel & 1) * 16;
        #pragma unroll
        for (int ks = 0; ks < 4; ks++) {
            uint32_t pa[4];
            ldsm_x4(pa[0], pa[1], pa[2], pa[3], pab + ks * 32);
            #pragma unroll
            for (int np = 0; np < 8; np++) {
                uint32_t b0, b1, b2, b3;
                ldsm_x4(b0, b1, b2, b3, vb0 + np * 16 * VROWB + ks * 32);
                mma_f16(oacc[2 * np],     pa, b0, b1);
                mma_f16(oacc[2 * np + 1], pa, b2, b3);
            }
        }
    }

    // ---- epilogue: O /= l, write ctx (fp16, feeds o-GEMM) ----
    const float inv0 = 1.f / l[0], inv1 = 1.f / l[1];
    __half* crow0 = g_ctx + (size_t)(b * SEQ + q0 + wq + qr) * DMODEL + h * DH + qc2;
    __half* crow1 = crow0 + 8 * DMODEL;
    #pragma unroll
    for (int nt = 0; nt < 16; nt++) {
        *(half2*)(crow0 + nt * 8) = __floats2half2_rn(oacc[nt][0] * inv0,
                                                      oacc[nt][1] * inv0);
        *(half2*)(crow1 + nt * 8) = __floats2half2_rn(oacc[nt][2] * inv1,
                                                      oacc[nt][3] * inv1);
    }
}

// ---------------------------------------------------------------------------
// Residual + LayerNorm
// ---------------------------------------------------------------------------
__global__ __launch_bounds__(256) void ln_kernel(
    const float* __restrict__ x, const float* __restrict__ ao,
    const float* __restrict__ gamma, const float* __restrict__ beta,
    float* __restrict__ out)
{
    __shared__ float ys[DMODEL];
    __shared__ float s_part[16];
    __shared__ float s_mu, s_rstd;

    const int r = blockIdx.x;
    const int t = threadIdx.x;
    const float* xr = x + (size_t)r * DMODEL;
    const float* ar = ao + (size_t)r * DMODEL;

    float sum = 0.f, sq = 0.f;
    for (int d = t; d < DMODEL; d += 256) {
        float y = xr[d] + ar[d];
        ys[d] = y;
        sum += y;
        sq  += y * y;
    }
    #pragma unroll
    for (int off = 16; off > 0; off >>= 1) {
        sum += __shfl_xor_sync(0xffffffffu, sum, off);
        sq  += __shfl_xor_sync(0xffffffffu, sq, off);
    }
    const int wid = t >> 5, lane = t & 31;
    if (lane == 0) { s_part[wid] = sum; s_part[8 + wid] = sq; }
    __syncthreads();
    if (t == 0) {
        float S = 0.f, Q = 0.f;
        #pragma unroll
        for (int w = 0; w < 8; w++) { S += s_part[w]; Q += s_part[8 + w]; }
        float mu  = S * (1.f / DMODEL);
        float var = Q * (1.f / DMODEL) - mu * mu;
        s_mu = mu;
        s_rstd = rsqrtf(var + 1e-5f);
    }
    __syncthreads();
    const float mu = s_mu, rstd = s_rstd;
    float* outr = out + (size_t)r * DMODEL;
    for (int d = t; d < DMODEL; d += 256)
        outr[d] = gamma[d] * (ys[d] - mu) * rstd + beta[d];
}

// ---------------------------------------------------------------------------
extern "C" void kernel_launch(void* const* d_in, const int* in_sizes, int n_in,
                              void* d_out, int out_size)
{
    const float* x     = (const float*)d_in[0];
    const float* Wq    = (const float*)d_in[1];
    const float* bq    = (const float*)d_in[2];
    const float* Wk    = (const float*)d_in[3];
    const float* bk    = (const float*)d_in[4];
    const float* Wv    = (const float*)d_in[5];
    const float* bv    = (const float*)d_in[6];
    const float* Wo    = (const float*)d_in[7];
    const float* bo    = (const float*)d_in[8];
    const float* gamma = (const float*)d_in[9];
    const float* beta  = (const float*)d_in[10];

    float* out    = (float*)d_out;
    float* ln_out = out;
    float* ao_out = out + CHUNK_E;
    float* k_out  = out + 2 * CHUNK_E;   // [B,H,S,Dh]
    float* v_out  = out + 3 * CHUNK_E;   // [B,H,S,Dh]

    __half *qptr = nullptr, *ctxptr = nullptr, *wtptr = nullptr, *xptr = nullptr;
    __half *krptr = nullptr, *vtptr = nullptr;
    cudaGetSymbolAddress((void**)&qptr,   g_q);
    cudaGetSymbolAddress((void**)&ctxptr, g_ctx);
    cudaGetSymbolAddress((void**)&wtptr,  g_wt);
    cudaGetSymbolAddress((void**)&xptr,   g_x);
    cudaGetSymbolAddress((void**)&krptr,  g_kr);
    cudaGetSymbolAddress((void**)&vtptr,  g_vt);
    __half* wt_o = wtptr + 3ULL * DMODEL * DMODEL;

    cudaFuncSetAttribute(gemm_qkv_kernel,
                         cudaFuncAttributeMaxDynamicSharedMemorySize, GEMM_SMEM);
    cudaFuncSetAttribute(gemm_o_kernel,
                         cudaFuncAttributeMaxDynamicSharedMemorySize, GEMM_SMEM);
    cudaFuncSetAttribute(attn_tc_kernel,
                         cudaFuncAttributeMaxDynamicSharedMemorySize, ATTN2_SMEM);

    // x -> fp16; fused 4-way W^T transpose to fp16 (order: q,k,v,o)
    tohalf_kernel<<<(int)(CHUNK_E / 8 / 256), 256>>>(x, xptr);
    dim3 tg(DMODEL / 32, DMODEL / 32, 4), tb(32, 8);
    transpose4_kernel<<<tg, tb>>>(Wq, Wk, Wv, Wo, wtptr);

    const float qscale = 0.08838834764831845f;  // 1/sqrt(128)

    // Fused Q/K/V projections
    dim3 qkv_grid(DMODEL / 128, NROWS / 128, 3);
    gemm_qkv_kernel<<<qkv_grid, 256, GEMM_SMEM>>>(
        xptr, wtptr, bq, bk, bv, qptr, k_out, v_out, krptr, qscale);

    // per-head V transpose to fp16 (attention B operand)
    dim3 vg(SEQ / 32, DH / 32, BATCH * NHEADS), vb2(32, 8);
    vtrans_kernel<<<vg, vb2>>>(v_out, vtptr);

    dim3 attn_grid(SEQ / BQ, NHEADS, BATCH);
    attn_tc_kernel<<<attn_grid, 256, ATTN2_SMEM>>>(krptr, vtptr);

    dim3 o_grid(DMODEL / 128, NROWS / 128);
    gemm_o_kernel<<<o_grid, 256, GEMM_SMEM>>>(ctxptr, wt_o, bo, ao_out);

    ln_kernel<<<NROWS, 256>>>(x, ao_out, gamma, beta, ln_out);
}